// round 1
// baseline (speedup 1.0000x reference)
#include <cuda_runtime.h>
#include <math.h>

// Problem constants (fixed by setup_inputs)
#define N_TE   20000
#define M_IND  1024
#define D_DIM  16
#define BS     64
#define NB     16            // M_IND / BS
#define SW     20032         // padded S width: N_TE + 32 (cols N_TE -> qu, N_TE+1 -> chole)
#define JITTER 1e-3f
#define EPSV   1e-9f

// Scratch (allocation-free: __device__ globals)
__device__ float g_L[M_IND * M_IND];          // K_mm, overwritten by L (lower)
__device__ float g_Zd[NB * BS * BS];          // per-diagonal-block inverses L_kk^{-1}
__device__ float g_S[M_IND * SW];             // K_tm^T (+2 RHS cols), overwritten by L^{-1} * (.)

// ---------------------------------------------------------------------------
// 1. K_mm = ard_kernel(xm, xm) + jitter*I
// ---------------------------------------------------------------------------
__global__ void build_kmm(const float* __restrict__ xm, const float* __restrict__ ls,
                          const float* __restrict__ sv) {
    int idx = blockIdx.x * blockDim.x + threadIdx.x;
    if (idx >= M_IND * M_IND) return;
    int r = idx / M_IND, c = idx % M_IND;
    float svv = fabsf(sv[0]);
    float d2 = 0.f;
#pragma unroll
    for (int d = 0; d < D_DIM; d++) {
        float il = 1.f / (fabsf(ls[d]) + EPSV);
        float diff = (xm[r * D_DIM + d] - xm[c * D_DIM + d]) * il;
        d2 += diff * diff;
    }
    float v = svv * __expf(-0.5f * d2);
    if (r == c) v += JITTER;
    g_L[idx] = v;
}

// ---------------------------------------------------------------------------
// 2. S init: S[m][n] = k(Xte_n, xm_m) for n<N; col N = qu_mean, col N+1 = chole
//    block tile: 64 test cols x 32 inducing rows, Xte/xm prescaled in smem
// ---------------------------------------------------------------------------
__global__ void init_S(const float* __restrict__ Xte, const float* __restrict__ xm,
                       const float* __restrict__ qu, const float* __restrict__ ch,
                       const float* __restrict__ ls, const float* __restrict__ sv) {
    __shared__ float Xs[64][D_DIM + 1];
    __shared__ float Ms[32][D_DIM + 1];
    int n0 = blockIdx.x * 64;
    int m0 = blockIdx.y * 32;
    int tid = threadIdx.x;

    for (int e = tid; e < 64 * D_DIM; e += 256) {
        int i = e / D_DIM, d = e % D_DIM;
        int n = n0 + i;
        float il = 1.f / (fabsf(ls[d]) + EPSV);
        Xs[i][d] = (n < N_TE) ? Xte[n * D_DIM + d] * il : 0.f;
    }
    for (int e = tid; e < 32 * D_DIM; e += 256) {
        int i = e / D_DIM, d = e % D_DIM;
        float il = 1.f / (fabsf(ls[d]) + EPSV);
        Ms[i][d] = xm[(m0 + i) * D_DIM + d] * il;
    }
    __syncthreads();

    float svv = fabsf(sv[0]);
    int tx = tid % 64;          // n within tile
    int ty = tid / 64;          // 0..3
    int n = n0 + tx;
#pragma unroll
    for (int mi = 0; mi < 8; mi++) {
        int ml = ty * 8 + mi;
        int m = m0 + ml;
        float outv;
        if (n < N_TE) {
            float d2 = 0.f;
#pragma unroll
            for (int d = 0; d < D_DIM; d++) {
                float diff = Xs[tx][d] - Ms[ml][d];
                d2 += diff * diff;
            }
            outv = svv * __expf(-0.5f * d2);
        } else if (n == N_TE)      outv = qu[m];
        else if (n == N_TE + 1)    outv = ch[m];
        else                       outv = 0.f;
        g_S[(size_t)m * SW + n] = outv;
    }
}

// ---------------------------------------------------------------------------
// 3. Diagonal-block Cholesky factor + explicit triangular inverse (one CTA)
// ---------------------------------------------------------------------------
__global__ void chol_diag_inv(int k) {
    __shared__ float Lb[BS][BS + 1];
    __shared__ float Zb[BS][BS + 1];
    int tid = threadIdx.x;     // 256
    int o = k * BS;

    for (int e = tid; e < BS * BS; e += 256) {
        int i = e / BS, j = e % BS;
        Lb[i][j] = g_L[(size_t)(o + i) * M_IND + o + j];
        Zb[i][j] = (i == j) ? 1.f : 0.f;
    }
    __syncthreads();

    int tx = tid % 16, ty = tid / 16;

    // factor (lower, right-looking)
    for (int j = 0; j < BS; j++) {
        if (tid == 0) Lb[j][j] = sqrtf(Lb[j][j]);
        __syncthreads();
        float inv = 1.f / Lb[j][j];
        for (int r = j + 1 + tid; r < BS; r += 256) Lb[r][j] *= inv;
        __syncthreads();
        for (int r = j + 1 + ty; r < BS; r += 16) {
            float lrj = Lb[r][j];
            for (int c = j + 1 + tx; c <= r; c += 16)
                Lb[r][c] -= lrj * Lb[c][j];
        }
        __syncthreads();
    }

    // invert: solve L Z = I (forward elimination, pivot-parallel)
    for (int i = 0; i < BS; i++) {
        float inv = 1.f / Lb[i][i];
        for (int j = tid; j <= i; j += 256) Zb[i][j] *= inv;
        __syncthreads();
        for (int r = i + 1 + ty; r < BS; r += 16) {
            float lri = Lb[r][i];
            for (int j = tx; j <= i; j += 16)
                Zb[r][j] -= lri * Zb[i][j];
        }
        __syncthreads();
    }

    for (int e = tid; e < BS * BS; e += 256) {
        int i = e / BS, j = e % BS;
        g_L[(size_t)(o + i) * M_IND + o + j] = Lb[i][j];
        g_Zd[k * BS * BS + e] = Zb[i][j];
    }
}

// ---------------------------------------------------------------------------
// 4. Panel TRSM as GEMM: P = A_panel * Zd_k^T (in place, one CTA per 64 rows)
// ---------------------------------------------------------------------------
__global__ void __launch_bounds__(256) panel_trsm(int k) {
    __shared__ float As[BS][BS + 1];
    __shared__ float Zs[BS][BS + 1];
    int o = k * BS;
    int r0 = o + BS + blockIdx.x * BS;
    int tid = threadIdx.x;

    for (int e = tid; e < BS * BS; e += 256) {
        int i = e / BS, j = e % BS;
        As[i][j] = g_L[(size_t)(r0 + i) * M_IND + o + j];
        Zs[i][j] = g_Zd[k * BS * BS + e];
    }
    __syncthreads();

    int tx = tid % 16, ty = tid / 16;
    float acc[4][4] = {};
    for (int c = 0; c < BS; c++) {
        float a[4], b[4];
#pragma unroll
        for (int ii = 0; ii < 4; ii++) a[ii] = As[ty * 4 + ii][c];
#pragma unroll
        for (int jj = 0; jj < 4; jj++) b[jj] = Zs[tx * 4 + jj][c];
#pragma unroll
        for (int ii = 0; ii < 4; ii++)
#pragma unroll
            for (int jj = 0; jj < 4; jj++) acc[ii][jj] += a[ii] * b[jj];
    }
#pragma unroll
    for (int ii = 0; ii < 4; ii++)
#pragma unroll
        for (int jj = 0; jj < 4; jj++)
            g_L[(size_t)(r0 + ty * 4 + ii) * M_IND + o + tx * 4 + jj] = acc[ii][jj];
}

// ---------------------------------------------------------------------------
// 5. SYRK trailing update: A[bi][bj] -= P_bi * P_bj^T (lower block triangle)
// ---------------------------------------------------------------------------
__global__ void __launch_bounds__(256) syrk_update(int k) {
    int bi = k + 1 + blockIdx.y, bj = k + 1 + blockIdx.x;
    if (bj > bi) return;
    __shared__ float Pa[BS][BS + 1];
    __shared__ float Pb[BS][BS + 1];
    int o = k * BS, tid = threadIdx.x;

    for (int e = tid; e < BS * BS; e += 256) {
        int i = e / BS, j = e % BS;
        Pa[i][j] = g_L[(size_t)(bi * BS + i) * M_IND + o + j];
        Pb[i][j] = g_L[(size_t)(bj * BS + i) * M_IND + o + j];
    }
    __syncthreads();

    int tx = tid % 16, ty = tid / 16;
    float acc[4][4] = {};
    for (int c = 0; c < BS; c++) {
        float a[4], b[4];
#pragma unroll
        for (int ii = 0; ii < 4; ii++) a[ii] = Pa[ty * 4 + ii][c];
#pragma unroll
        for (int jj = 0; jj < 4; jj++) b[jj] = Pb[tx * 4 + jj][c];
#pragma unroll
        for (int ii = 0; ii < 4; ii++)
#pragma unroll
            for (int jj = 0; jj < 4; jj++) acc[ii][jj] += a[ii] * b[jj];
    }
#pragma unroll
    for (int ii = 0; ii < 4; ii++)
#pragma unroll
        for (int jj = 0; jj < 4; jj++) {
            size_t idx = (size_t)(bi * BS + ty * 4 + ii) * M_IND + bj * BS + tx * 4 + jj;
            g_L[idx] -= acc[ii][jj];
        }
}

// ---------------------------------------------------------------------------
// 6. Blocked forward solve on S: S[kb] = Zd_kb * (S[kb] - L[kb,<kb] @ S[<kb])
//    One CTA per 64-wide column stripe; 4x4 register micro-tiles, float4 LDS.
// ---------------------------------------------------------------------------
__global__ void __launch_bounds__(256) trsm_S(int kb) {
    __shared__ float Asm[BS][BS + 4];   // L^T chunk, then Zd^T
    __shared__ float Bsm[BS][BS + 4];   // S chunk,  then T
    int o = kb * BS;
    int n0 = blockIdx.x * BS;
    int tid = threadIdx.x;
    int tx = tid % 16, ty = tid / 16;

    // T := S[o..o+63][n0..n0+63]
    float acc[4][4];
#pragma unroll
    for (int ii = 0; ii < 4; ii++) {
        float4 v = *(const float4*)&g_S[(size_t)(o + ty * 4 + ii) * SW + n0 + tx * 4];
        acc[ii][0] = v.x; acc[ii][1] = v.y; acc[ii][2] = v.z; acc[ii][3] = v.w;
    }

    // T -= L[o rows][0..o) @ S[0..o)
    for (int j0 = 0; j0 < o; j0 += BS) {
        for (int e = tid; e < BS * BS; e += 256) {
            int c = e % BS, i = e / BS;
            Asm[c][i] = g_L[(size_t)(o + i) * M_IND + j0 + c];     // transposed store
        }
        for (int e = tid; e < BS * BS; e += 256) {
            int n = e % BS, c = e / BS;
            Bsm[c][n] = g_S[(size_t)(j0 + c) * SW + n0 + n];
        }
        __syncthreads();
        for (int c = 0; c < BS; c++) {
            float4 a4 = *(const float4*)&Asm[c][ty * 4];
            float4 b4 = *(const float4*)&Bsm[c][tx * 4];
            float a[4] = {a4.x, a4.y, a4.z, a4.w};
            float b[4] = {b4.x, b4.y, b4.z, b4.w};
#pragma unroll
            for (int ii = 0; ii < 4; ii++)
#pragma unroll
                for (int jj = 0; jj < 4; jj++) acc[ii][jj] -= a[ii] * b[jj];
        }
        __syncthreads();
    }

    // S[kb] = Zd_kb @ T
#pragma unroll
    for (int ii = 0; ii < 4; ii++)
        *(float4*)&Bsm[ty * 4 + ii][tx * 4] =
            make_float4(acc[ii][0], acc[ii][1], acc[ii][2], acc[ii][3]);
    for (int e = tid; e < BS * BS; e += 256) {
        int c = e % BS, i = e / BS;
        Asm[c][i] = g_Zd[kb * BS * BS + i * BS + c];               // transposed store
    }
    __syncthreads();

    float r2[4][4] = {};
    for (int c = 0; c < BS; c++) {
        float4 a4 = *(const float4*)&Asm[c][ty * 4];
        float4 b4 = *(const float4*)&Bsm[c][tx * 4];
        float a[4] = {a4.x, a4.y, a4.z, a4.w};
        float b[4] = {b4.x, b4.y, b4.z, b4.w};
#pragma unroll
        for (int ii = 0; ii < 4; ii++)
#pragma unroll
            for (int jj = 0; jj < 4; jj++) r2[ii][jj] += a[ii] * b[jj];
    }
#pragma unroll
    for (int ii = 0; ii < 4; ii++)
        *(float4*)&g_S[(size_t)(o + ty * 4 + ii) * SW + n0 + tx * 4] =
            make_float4(r2[ii][0], r2[ii][1], r2[ii][2], r2[ii][3]);
}

// ---------------------------------------------------------------------------
// 7. Finalize: mean_n = S_col.y1 ; yvar_n = |sv| - ||S_col||^2 + (S_col.y2)^2
// ---------------------------------------------------------------------------
__global__ void finalize(float* __restrict__ out, const float* __restrict__ sv) {
    __shared__ float sy1[M_IND];
    __shared__ float sy2[M_IND];
    for (int e = threadIdx.x; e < M_IND; e += 256) {
        sy1[e] = g_S[(size_t)e * SW + N_TE];
        sy2[e] = g_S[(size_t)e * SW + N_TE + 1];
    }
    __syncthreads();

    int n = blockIdx.x * blockDim.x + threadIdx.x;
    if (n >= N_TE) return;
    float q = 0.f, mm = 0.f, vv = 0.f;
    for (int m = 0; m < M_IND; m++) {
        float s = g_S[(size_t)m * SW + n];
        q += s * s;
        mm += s * sy1[m];
        vv += s * sy2[m];
    }
    float svv = fabsf(sv[0]);
    out[n] = mm;
    out[N_TE + n] = svv - q + vv * vv;
}

// ---------------------------------------------------------------------------
extern "C" void kernel_launch(void* const* d_in, const int* in_sizes, int n_in,
                              void* d_out, int out_size) {
    const float* Xte = (const float*)d_in[0];
    const float* xm  = (const float*)d_in[1];
    const float* qu  = (const float*)d_in[2];
    const float* ch  = (const float*)d_in[3];
    const float* ls  = (const float*)d_in[4];
    const float* sv  = (const float*)d_in[5];
    float* out = (float*)d_out;

    build_kmm<<<(M_IND * M_IND + 255) / 256, 256>>>(xm, ls, sv);
    init_S<<<dim3(SW / 64, M_IND / 32), 256>>>(Xte, xm, qu, ch, ls, sv);

    for (int k = 0; k < NB; k++) {
        chol_diag_inv<<<1, 256>>>(k);
        if (k < NB - 1) {
            panel_trsm<<<NB - 1 - k, 256>>>(k);
            int t = NB - 1 - k;
            syrk_update<<<dim3(t, t), 256>>>(k);
        }
    }
    for (int kb = 0; kb < NB; kb++)
        trsm_S<<<SW / BS, 256>>>(kb);

    finalize<<<(N_TE + 255) / 256, 256>>>(out, sv);
}

// round 2
// speedup vs baseline: 1.1997x; 1.1997x over previous
#include <cuda_runtime.h>
#include <math.h>

// Problem constants (fixed by setup_inputs)
#define N_TE   20000
#define M_IND  1024
#define D_DIM  16
#define BS     64
#define NB     16            // M_IND / BS
#define SW     20096         // padded S width: 157*128 (col N_TE -> qu, N_TE+1 -> chole)
#define JITTER 1e-3f
#define EPSV   1e-9f

// Scratch (allocation-free: __device__ globals)
__device__ float g_L[M_IND * M_IND];          // K_mm, overwritten by L (lower)
__device__ float g_W[M_IND * M_IND];          // L^{-1} (block-lower)
__device__ float g_Zd[NB * BS * BS];          // per-diagonal-block inverses L_kk^{-1}
__device__ float g_S[(size_t)M_IND * SW];     // K_tm^T (+2 RHS cols)
__device__ float g_S2[(size_t)M_IND * SW];    // W @ g_S
__device__ float g_tmp[512 * 512];            // doubling-inversion temp

// ---------------------------------------------------------------------------
// 1. K_mm = ard_kernel(xm, xm) + jitter*I
// ---------------------------------------------------------------------------
__global__ void build_kmm(const float* __restrict__ xm, const float* __restrict__ ls,
                          const float* __restrict__ sv) {
    int idx = blockIdx.x * blockDim.x + threadIdx.x;
    if (idx >= M_IND * M_IND) return;
    int r = idx / M_IND, c = idx % M_IND;
    float svv = fabsf(sv[0]);
    float d2 = 0.f;
#pragma unroll
    for (int d = 0; d < D_DIM; d++) {
        float il = 1.f / (fabsf(ls[d]) + EPSV);
        float diff = (xm[r * D_DIM + d] - xm[c * D_DIM + d]) * il;
        d2 += diff * diff;
    }
    float v = svv * __expf(-0.5f * d2);
    if (r == c) v += JITTER;
    g_L[idx] = v;
}

// ---------------------------------------------------------------------------
// 2. S init: S[m][n] = k(Xte_n, xm_m) for n<N; col N = qu_mean, col N+1 = chole
// ---------------------------------------------------------------------------
__global__ void init_S(const float* __restrict__ Xte, const float* __restrict__ xm,
                       const float* __restrict__ qu, const float* __restrict__ ch,
                       const float* __restrict__ ls, const float* __restrict__ sv) {
    __shared__ float Xs[64][D_DIM + 1];
    __shared__ float Ms[32][D_DIM + 1];
    int n0 = blockIdx.x * 64;
    int m0 = blockIdx.y * 32;
    int tid = threadIdx.x;

    for (int e = tid; e < 64 * D_DIM; e += 256) {
        int i = e / D_DIM, d = e % D_DIM;
        int n = n0 + i;
        float il = 1.f / (fabsf(ls[d]) + EPSV);
        Xs[i][d] = (n < N_TE) ? Xte[n * D_DIM + d] * il : 0.f;
    }
    for (int e = tid; e < 32 * D_DIM; e += 256) {
        int i = e / D_DIM, d = e % D_DIM;
        float il = 1.f / (fabsf(ls[d]) + EPSV);
        Ms[i][d] = xm[(m0 + i) * D_DIM + d] * il;
    }
    __syncthreads();

    float svv = fabsf(sv[0]);
    int tx = tid % 64;
    int ty = tid / 64;
    int n = n0 + tx;
#pragma unroll
    for (int mi = 0; mi < 8; mi++) {
        int ml = ty * 8 + mi;
        int m = m0 + ml;
        float outv;
        if (n < N_TE) {
            float d2 = 0.f;
#pragma unroll
            for (int d = 0; d < D_DIM; d++) {
                float diff = Xs[tx][d] - Ms[ml][d];
                d2 += diff * diff;
            }
            outv = svv * __expf(-0.5f * d2);
        } else if (n == N_TE)      outv = qu[m];
        else if (n == N_TE + 1)    outv = ch[m];
        else                       outv = 0.f;
        g_S[(size_t)m * SW + n] = outv;
    }
}

// ---------------------------------------------------------------------------
// 3. Diagonal-block 0 Cholesky factor + triangular inverse (one CTA, once)
// ---------------------------------------------------------------------------
__global__ void chol_diag_inv(int k) {
    __shared__ float Lb[BS][BS + 1];
    __shared__ float Zb[BS][BS + 1];
    int tid = threadIdx.x;
    int o = k * BS;

    for (int e = tid; e < BS * BS; e += 256) {
        int i = e / BS, j = e % BS;
        Lb[i][j] = g_L[(size_t)(o + i) * M_IND + o + j];
        Zb[i][j] = (i == j) ? 1.f : 0.f;
    }
    __syncthreads();

    int tx = tid % 16, ty = tid / 16;

    // deferred-scale factorization: 1 sync per pivot
    for (int j = 0; j < BS - 1; j++) {
        float inv = 1.f / Lb[j][j];
        for (int r = j + 1 + ty; r < BS; r += 16) {
            float lrj = Lb[r][j] * inv;
            for (int c = j + 1 + tx; c <= r; c += 16)
                Lb[r][c] -= lrj * Lb[c][j];
        }
        __syncthreads();
    }
    // scale pass
    float vals[16];
    for (int e = tid, q = 0; e < BS * BS; e += 256, q++) {
        int r = e / BS, c = e % BS;
        float v = Lb[r][c];
        if (c < r)       v *= rsqrtf(Lb[c][c]);
        else if (c == r) v = sqrtf(v);
        vals[q] = v;
    }
    __syncthreads();
    for (int e = tid, q = 0; e < BS * BS; e += 256, q++) {
        int r = e / BS, c = e % BS;
        Lb[r][c] = vals[q];
    }
    __syncthreads();

    // invert: solve L Z = I
    for (int i = 0; i < BS; i++) {
        float inv = 1.f / Lb[i][i];
        for (int j = tid; j <= i; j += 256) Zb[i][j] *= inv;
        __syncthreads();
        for (int r = i + 1 + ty; r < BS; r += 16) {
            float lri = Lb[r][i];
            for (int j = tx; j <= i; j += 16)
                Zb[r][j] -= lri * Zb[i][j];
        }
        __syncthreads();
    }

    for (int e = tid; e < BS * BS; e += 256) {
        int i = e / BS, j = e % BS;
        g_L[(size_t)(o + i) * M_IND + o + j] = Lb[i][j];
        g_Zd[k * BS * BS + e] = Zb[i][j];
    }
}

// ---------------------------------------------------------------------------
// 4. Panel TRSM as GEMM: P = A_panel * Zd_k^T (in place)
// ---------------------------------------------------------------------------
__global__ void __launch_bounds__(256) panel_trsm(int k) {
    __shared__ float As[BS][BS + 1];
    __shared__ float Zs[BS][BS + 1];
    int o = k * BS;
    int r0 = o + BS + blockIdx.x * BS;
    int tid = threadIdx.x;

    for (int e = tid; e < BS * BS; e += 256) {
        int i = e / BS, j = e % BS;
        As[i][j] = g_L[(size_t)(r0 + i) * M_IND + o + j];
        Zs[i][j] = g_Zd[k * BS * BS + e];
    }
    __syncthreads();

    int tx = tid % 16, ty = tid / 16;
    float acc[4][4] = {};
    for (int c = 0; c < BS; c++) {
        float a[4], b[4];
#pragma unroll
        for (int ii = 0; ii < 4; ii++) a[ii] = As[ty * 4 + ii][c];
#pragma unroll
        for (int jj = 0; jj < 4; jj++) b[jj] = Zs[tx * 4 + jj][c];
#pragma unroll
        for (int ii = 0; ii < 4; ii++)
#pragma unroll
            for (int jj = 0; jj < 4; jj++) acc[ii][jj] += a[ii] * b[jj];
    }
#pragma unroll
    for (int ii = 0; ii < 4; ii++)
#pragma unroll
        for (int jj = 0; jj < 4; jj++)
            g_L[(size_t)(r0 + ty * 4 + ii) * M_IND + o + tx * 4 + jj] = acc[ii][jj];
}

// ---------------------------------------------------------------------------
// 5. SYRK trailing update, with the diagonal CTA (k+1,k+1) also factoring +
//    inverting its freshly-updated block (produces L(k+1,k+1), Zd(k+1)).
// ---------------------------------------------------------------------------
__global__ void __launch_bounds__(256) syrk_fused(int k) {
    int bi = k + 1 + blockIdx.y, bj = k + 1 + blockIdx.x;
    if (bj > bi) return;
    __shared__ float Pa[BS][BS + 1];
    __shared__ float Pb[BS][BS + 1];
    int o = k * BS, tid = threadIdx.x;

    for (int e = tid; e < BS * BS; e += 256) {
        int i = e / BS, j = e % BS;
        Pa[i][j] = g_L[(size_t)(bi * BS + i) * M_IND + o + j];
        Pb[i][j] = g_L[(size_t)(bj * BS + i) * M_IND + o + j];
    }
    __syncthreads();

    int tx = tid % 16, ty = tid / 16;
    float acc[4][4];
#pragma unroll
    for (int ii = 0; ii < 4; ii++)
#pragma unroll
        for (int jj = 0; jj < 4; jj++)
            acc[ii][jj] = g_L[(size_t)(bi * BS + ty * 4 + ii) * M_IND + bj * BS + tx * 4 + jj];

    for (int c = 0; c < BS; c++) {
        float a[4], b[4];
#pragma unroll
        for (int ii = 0; ii < 4; ii++) a[ii] = Pa[ty * 4 + ii][c];
#pragma unroll
        for (int jj = 0; jj < 4; jj++) b[jj] = Pb[tx * 4 + jj][c];
#pragma unroll
        for (int ii = 0; ii < 4; ii++)
#pragma unroll
            for (int jj = 0; jj < 4; jj++) acc[ii][jj] -= a[ii] * b[jj];
    }

    bool is_diag_cta = (blockIdx.x == 0 && blockIdx.y == 0);   // (k+1,k+1)
    if (!is_diag_cta) {
#pragma unroll
        for (int ii = 0; ii < 4; ii++)
#pragma unroll
            for (int jj = 0; jj < 4; jj++)
                g_L[(size_t)(bi * BS + ty * 4 + ii) * M_IND + bj * BS + tx * 4 + jj] = acc[ii][jj];
        return;
    }

    // ---- diagonal CTA: factor + invert the updated block in smem ----
    __syncthreads();
#pragma unroll
    for (int ii = 0; ii < 4; ii++)
#pragma unroll
        for (int jj = 0; jj < 4; jj++)
            Pa[ty * 4 + ii][tx * 4 + jj] = acc[ii][jj];
    for (int e = tid; e < BS * BS; e += 256) {
        int i = e / BS, j = e % BS;
        Pb[i][j] = (i == j) ? 1.f : 0.f;
    }
    __syncthreads();

    // deferred-scale Cholesky
    for (int j = 0; j < BS - 1; j++) {
        float inv = 1.f / Pa[j][j];
        for (int r = j + 1 + ty; r < BS; r += 16) {
            float lrj = Pa[r][j] * inv;
            for (int c = j + 1 + tx; c <= r; c += 16)
                Pa[r][c] -= lrj * Pa[c][j];
        }
        __syncthreads();
    }
    float vals[16];
    for (int e = tid, q = 0; e < BS * BS; e += 256, q++) {
        int r = e / BS, c = e % BS;
        float v = Pa[r][c];
        if (c < r)       v *= rsqrtf(Pa[c][c]);
        else if (c == r) v = sqrtf(v);
        vals[q] = v;
    }
    __syncthreads();
    for (int e = tid, q = 0; e < BS * BS; e += 256, q++) {
        int r = e / BS, c = e % BS;
        Pa[r][c] = vals[q];
    }
    __syncthreads();

    // invert: L Z = I
    for (int i = 0; i < BS; i++) {
        float inv = 1.f / Pa[i][i];
        for (int j = tid; j <= i; j += 256) Pb[i][j] *= inv;
        __syncthreads();
        for (int r = i + 1 + ty; r < BS; r += 16) {
            float lri = Pa[r][i];
            for (int j = tx; j <= i; j += 16)
                Pb[r][j] -= lri * Pb[i][j];
        }
        __syncthreads();
    }

    for (int e = tid; e < BS * BS; e += 256)
        g_Zd[(k + 1) * BS * BS + e] = Pb[e / BS][e % BS];
}

// ---------------------------------------------------------------------------
// 6. W = L^{-1} via recursive doubling.
//    winit: W = blockdiag(Zd). Then per level (s = 64<<l):
//      tri_a: C_p = T21_p @ W11_p ; tri_b: W21_p = -W22_p @ C_p
// ---------------------------------------------------------------------------
__global__ void winit() {
    int idx = blockIdx.x * blockDim.x + threadIdx.x;
    if (idx >= M_IND * M_IND) return;
    int r = idx / M_IND, c = idx % M_IND;
    float v = 0.f;
    if (r / BS == c / BS)
        v = g_Zd[(r / BS) * BS * BS + (r % BS) * BS + (c % BS)];
    g_W[idx] = v;
}

__global__ void __launch_bounds__(256) tri_a(int l) {
    int s = 64 << l;
    int p = blockIdx.x, tr = blockIdx.y, tc = blockIdx.z;
    int base = p * 2 * s;
    __shared__ float As[BS][BS + 1];
    __shared__ float Bs[BS][BS + 1];
    int tid = threadIdx.x, tx = tid % 16, ty = tid / 16;
    float acc[4][4] = {};

    for (int k0 = 0; k0 < s; k0 += BS) {
        for (int e = tid; e < BS * BS; e += 256) {
            int i = e / BS, j = e % BS;
            As[i][j] = g_L[(size_t)(base + s + tr * BS + i) * M_IND + base + k0 + j];
            Bs[i][j] = g_W[(size_t)(base + k0 + i) * M_IND + base + tc * BS + j];
        }
        __syncthreads();
        for (int c = 0; c < BS; c++) {
            float a[4], b[4];
#pragma unroll
            for (int ii = 0; ii < 4; ii++) a[ii] = As[ty * 4 + ii][c];
#pragma unroll
            for (int jj = 0; jj < 4; jj++) b[jj] = Bs[c][tx * 4 + jj];
#pragma unroll
            for (int ii = 0; ii < 4; ii++)
#pragma unroll
                for (int jj = 0; jj < 4; jj++) acc[ii][jj] += a[ii] * b[jj];
        }
        __syncthreads();
    }
#pragma unroll
    for (int ii = 0; ii < 4; ii++)
#pragma unroll
        for (int jj = 0; jj < 4; jj++)
            g_tmp[(size_t)p * s * s + (tr * BS + ty * 4 + ii) * s + tc * BS + tx * 4 + jj] = acc[ii][jj];
}

__global__ void __launch_bounds__(256) tri_b(int l) {
    int s = 64 << l;
    int p = blockIdx.x, tr = blockIdx.y, tc = blockIdx.z;
    int base = p * 2 * s;
    __shared__ float As[BS][BS + 1];
    __shared__ float Bs[BS][BS + 1];
    int tid = threadIdx.x, tx = tid % 16, ty = tid / 16;
    float acc[4][4] = {};

    for (int k0 = 0; k0 < s; k0 += BS) {
        for (int e = tid; e < BS * BS; e += 256) {
            int i = e / BS, j = e % BS;
            As[i][j] = g_W[(size_t)(base + s + tr * BS + i) * M_IND + base + s + k0 + j];
            Bs[i][j] = g_tmp[(size_t)p * s * s + (k0 + i) * s + tc * BS + j];
        }
        __syncthreads();
        for (int c = 0; c < BS; c++) {
            float a[4], b[4];
#pragma unroll
            for (int ii = 0; ii < 4; ii++) a[ii] = As[ty * 4 + ii][c];
#pragma unroll
            for (int jj = 0; jj < 4; jj++) b[jj] = Bs[c][tx * 4 + jj];
#pragma unroll
            for (int ii = 0; ii < 4; ii++)
#pragma unroll
                for (int jj = 0; jj < 4; jj++) acc[ii][jj] += a[ii] * b[jj];
        }
        __syncthreads();
    }
#pragma unroll
    for (int ii = 0; ii < 4; ii++)
#pragma unroll
        for (int jj = 0; jj < 4; jj++)
            g_W[(size_t)(base + s + tr * BS + ty * 4 + ii) * M_IND + base + tc * BS + tx * 4 + jj]
                = -acc[ii][jj];
}

// ---------------------------------------------------------------------------
// 7. S2 = W @ S (block-lower W: k-range limited). 128x128x16 tiles, 8x8 micro.
// ---------------------------------------------------------------------------
__global__ void __launch_bounds__(256) gemm_S() {
    __shared__ float Wsm[16][128 + 4];
    __shared__ float Ksm[16][128 + 4];
    int n0 = blockIdx.x * 128;
    int mb = 7 - blockIdx.y;              // heavy row-blocks first
    int m0 = mb * 128;
    int KMAX = m0 + 128;
    int tid = threadIdx.x;
    int tx = tid % 16, ty = tid / 16;

    float acc[8][8] = {};

    int lm = tid / 2, lk = (tid % 2) * 8;     // W loader: 8 floats along k
    int kr = tid / 16, kc = (tid % 16) * 8;   // K loader: 8 floats along n

    for (int k0 = 0; k0 < KMAX; k0 += 16) {
        float4 wa = *(const float4*)&g_W[(size_t)(m0 + lm) * M_IND + k0 + lk];
        float4 wb = *(const float4*)&g_W[(size_t)(m0 + lm) * M_IND + k0 + lk + 4];
        Wsm[lk + 0][lm] = wa.x; Wsm[lk + 1][lm] = wa.y;
        Wsm[lk + 2][lm] = wa.z; Wsm[lk + 3][lm] = wa.w;
        Wsm[lk + 4][lm] = wb.x; Wsm[lk + 5][lm] = wb.y;
        Wsm[lk + 6][lm] = wb.z; Wsm[lk + 7][lm] = wb.w;
        *(float4*)&Ksm[kr][kc]     = *(const float4*)&g_S[(size_t)(k0 + kr) * SW + n0 + kc];
        *(float4*)&Ksm[kr][kc + 4] = *(const float4*)&g_S[(size_t)(k0 + kr) * SW + n0 + kc + 4];
        __syncthreads();

#pragma unroll
        for (int kk = 0; kk < 16; kk++) {
            float4 a0 = *(const float4*)&Wsm[kk][ty * 8];
            float4 a1 = *(const float4*)&Wsm[kk][ty * 8 + 4];
            float4 b0 = *(const float4*)&Ksm[kk][tx * 8];
            float4 b1 = *(const float4*)&Ksm[kk][tx * 8 + 4];
            float a[8] = {a0.x, a0.y, a0.z, a0.w, a1.x, a1.y, a1.z, a1.w};
            float b[8] = {b0.x, b0.y, b0.z, b0.w, b1.x, b1.y, b1.z, b1.w};
#pragma unroll
            for (int ii = 0; ii < 8; ii++)
#pragma unroll
                for (int jj = 0; jj < 8; jj++)
                    acc[ii][jj] += a[ii] * b[jj];
        }
        __syncthreads();
    }

#pragma unroll
    for (int ii = 0; ii < 8; ii++) {
        size_t row = (size_t)(m0 + ty * 8 + ii) * SW + n0 + tx * 8;
        *(float4*)&g_S2[row]     = make_float4(acc[ii][0], acc[ii][1], acc[ii][2], acc[ii][3]);
        *(float4*)&g_S2[row + 4] = make_float4(acc[ii][4], acc[ii][5], acc[ii][6], acc[ii][7]);
    }
}

// ---------------------------------------------------------------------------
// 8. Finalize: mean_n = S2_col.y1 ; yvar_n = |sv| - ||S2_col||^2 + (S2_col.y2)^2
// ---------------------------------------------------------------------------
__global__ void finalize(float* __restrict__ out, const float* __restrict__ sv) {
    __shared__ float sy1[M_IND];
    __shared__ float sy2[M_IND];
    for (int e = threadIdx.x; e < M_IND; e += 256) {
        sy1[e] = g_S2[(size_t)e * SW + N_TE];
        sy2[e] = g_S2[(size_t)e * SW + N_TE + 1];
    }
    __syncthreads();

    int n = blockIdx.x * blockDim.x + threadIdx.x;
    if (n >= N_TE) return;
    float q = 0.f, mm = 0.f, vv = 0.f;
    for (int m = 0; m < M_IND; m++) {
        float s = g_S2[(size_t)m * SW + n];
        q += s * s;
        mm += s * sy1[m];
        vv += s * sy2[m];
    }
    float svv = fabsf(sv[0]);
    out[n] = mm;
    out[N_TE + n] = svv - q + vv * vv;
}

// ---------------------------------------------------------------------------
extern "C" void kernel_launch(void* const* d_in, const int* in_sizes, int n_in,
                              void* d_out, int out_size) {
    const float* Xte = (const float*)d_in[0];
    const float* xm  = (const float*)d_in[1];
    const float* qu  = (const float*)d_in[2];
    const float* ch  = (const float*)d_in[3];
    const float* ls  = (const float*)d_in[4];
    const float* sv  = (const float*)d_in[5];
    float* out = (float*)d_out;

    build_kmm<<<(M_IND * M_IND + 255) / 256, 256>>>(xm, ls, sv);
    init_S<<<dim3(SW / 64, M_IND / 32), 256>>>(Xte, xm, qu, ch, ls, sv);

    chol_diag_inv<<<1, 256>>>(0);
    for (int k = 0; k < NB - 1; k++) {
        panel_trsm<<<NB - 1 - k, 256>>>(k);
        int t = NB - 1 - k;
        syrk_fused<<<dim3(t, t), 256>>>(k);
    }

    winit<<<(M_IND * M_IND + 255) / 256, 256>>>();
    for (int l = 0; l < 4; l++) {
        int t = 1 << l, pairs = 8 >> l;
        tri_a<<<dim3(pairs, t, t), 256>>>(l);
        tri_b<<<dim3(pairs, t, t), 256>>>(l);
    }

    gemm_S<<<dim3(SW / 128, 8), 256>>>();
    finalize<<<(N_TE + 255) / 256, 256>>>(out, sv);
}

// round 3
// speedup vs baseline: 1.4115x; 1.1765x over previous
#include <cuda_runtime.h>
#include <math.h>

// Problem constants (fixed by setup_inputs)
#define N_TE   20000
#define M_IND  1024
#define D_DIM  16
#define BS     64
#define NB     16
#define SW     20096          // 157*128 padded width
#define JITTER 1e-3f
#define EPSV   1e-9f
#define NBLK   120            // persistent grid (<= SM count, co-resident)

// Scratch (allocation-free: __device__ globals)
__device__ float g_L[M_IND * M_IND];
__device__ float g_W[M_IND * M_IND];
__device__ float g_Zd[NB * BS * BS];
__device__ float g_S[(size_t)M_IND * SW];
__device__ float g_tmp[512 * 512];
__device__ float g_xs[M_IND * D_DIM];
__device__ float g_nm[M_IND];
__device__ float g_a1[M_IND];
__device__ float g_a2[M_IND];
__device__ float g_q[8 * SW];
__device__ float g_mm[8 * SW];
__device__ float g_vv[8 * SW];
__device__ unsigned g_cnt = 0;
__device__ volatile unsigned g_epoch = 0;

// ---------------------------------------------------------------------------
// Software grid barrier (monotonic epoch: safe across graph replays)
// ---------------------------------------------------------------------------
__device__ __forceinline__ void gbar(unsigned& sense) {
    __syncthreads();
    if (threadIdx.x == 0) {
        unsigned target = sense + 1;
        __threadfence();
        unsigned old = atomicAdd(&g_cnt, 1u);
        if (old == NBLK - 1) {
            atomicExch(&g_cnt, 0u);
            __threadfence();
            g_epoch = target;
        } else {
            while (g_epoch < target) { }
            __threadfence();
        }
    }
    __syncthreads();
    sense += 1;
}

// ---------------------------------------------------------------------------
// Diagonal 64x64 block: deferred-scale Cholesky factor + triangular inverse.
// Operates on SA (input block -> L), SB (-> L^{-1}); writes g_Zd[kout].
// All 256 threads of the calling CTA must enter.
// ---------------------------------------------------------------------------
__device__ void factor_inverse(float (&Lb)[BS][BS + 1], float (&Zb)[BS][BS + 1], int kout) {
    int tid = threadIdx.x, tx = tid % 16, ty = tid / 16;
    for (int e = tid; e < BS * BS; e += 256)
        Zb[e / BS][e % BS] = (e / BS == e % BS) ? 1.f : 0.f;
    __syncthreads();

    // deferred-scale elimination: 1 sync per pivot
    for (int j = 0; j < BS - 1; j++) {
        float inv = 1.f / Lb[j][j];
        for (int r = j + 1 + ty; r < BS; r += 16) {
            float lrj = Lb[r][j] * inv;
            for (int c = j + 1 + tx; c <= r; c += 16)
                Lb[r][c] -= lrj * Lb[c][j];
        }
        __syncthreads();
    }
    float vals[16];
    int q = 0;
    for (int e = tid; e < BS * BS; e += 256, q++) {
        int r = e / BS, c = e % BS;
        float v = Lb[r][c];
        if (c < r)       v *= rsqrtf(Lb[c][c]);
        else if (c == r) v = sqrtf(v);
        vals[q] = v;
    }
    __syncthreads();
    q = 0;
    for (int e = tid; e < BS * BS; e += 256, q++)
        Lb[e / BS][e % BS] = vals[q];
    __syncthreads();

    // invert: L Z = I
    for (int i = 0; i < BS; i++) {
        float inv = 1.f / Lb[i][i];
        for (int j = tid; j <= i; j += 256) Zb[i][j] *= inv;
        __syncthreads();
        for (int r = i + 1 + ty; r < BS; r += 16) {
            float lri = Lb[r][i];
            for (int j = tx; j <= i; j += 16)
                Zb[r][j] -= lri * Zb[i][j];
        }
        __syncthreads();
    }
    for (int e = tid; e < BS * BS; e += 256)
        g_Zd[kout * BS * BS + e] = Zb[e / BS][e % BS];
    __syncthreads();
}

// ---------------------------------------------------------------------------
// Persistent kernel: K_mm -> Cholesky(L, Zd) -> W = L^{-1} -> a1, a2
// ---------------------------------------------------------------------------
__global__ void __launch_bounds__(256) fact_kernel(const float* __restrict__ xm,
                                                   const float* __restrict__ qu,
                                                   const float* __restrict__ ch,
                                                   const float* __restrict__ ls,
                                                   const float* __restrict__ sv) {
    __shared__ float SA[BS][BS + 1];
    __shared__ float SB[BS][BS + 1];
    __shared__ unsigned s0;
    int tid = threadIdx.x, bid = blockIdx.x;
    if (tid == 0) s0 = g_epoch;
    __syncthreads();
    unsigned sense = s0;

    int gthread = bid * 256 + tid;
    int tx = tid % 16, ty = tid / 16;

    // phase: pre-scaled xm rows + norms
    for (int m = gthread; m < M_IND; m += NBLK * 256) {
        float nrm = 0.f;
#pragma unroll
        for (int d = 0; d < D_DIM; d++) {
            float il = 1.f / (fabsf(ls[d]) + EPSV);
            float v = xm[m * D_DIM + d] * il;
            g_xs[m * D_DIM + d] = v;
            nrm += v * v;
        }
        g_nm[m] = nrm;
    }
    gbar(sense);

    // phase: K_mm = |sv| exp(-0.5 d2) + jitter I
    float svv = fabsf(sv[0]);
    for (int idx = gthread; idx < M_IND * M_IND; idx += NBLK * 256) {
        int r = idx / M_IND, c = idx % M_IND;
        float dot = 0.f;
#pragma unroll
        for (int d = 0; d < D_DIM; d++)
            dot += g_xs[r * D_DIM + d] * g_xs[c * D_DIM + d];
        float d2 = fmaxf(g_nm[r] + g_nm[c] - 2.f * dot, 0.f);
        float v = svv * __expf(-0.5f * d2);
        if (r == c) v += JITTER;
        g_L[idx] = v;
    }
    gbar(sense);

    // diag block 0
    if (bid == 0) {
        for (int e = tid; e < BS * BS; e += 256)
            SA[e / BS][e % BS] = g_L[(size_t)(e / BS) * M_IND + (e % BS)];
        __syncthreads();
        factor_inverse(SA, SB, 0);
    }
    gbar(sense);

    // Cholesky steps
    for (int k = 0; k < NB - 1; k++) {
        int o = k * BS, t = NB - 1 - k;

        // panel phase: P = A * Zd_k^T
        for (int pidx = bid; pidx < t; pidx += NBLK) {
            int r0 = o + BS + pidx * BS;
            for (int e = tid; e < BS * BS; e += 256) {
                int i = e / BS, j = e % BS;
                SA[i][j] = g_L[(size_t)(r0 + i) * M_IND + o + j];
                SB[i][j] = g_Zd[k * BS * BS + e];
            }
            __syncthreads();
            float acc[4][4] = {};
            for (int c = 0; c < BS; c++) {
                float a[4], b[4];
#pragma unroll
                for (int ii = 0; ii < 4; ii++) a[ii] = SA[ty * 4 + ii][c];
#pragma unroll
                for (int jj = 0; jj < 4; jj++) b[jj] = SB[tx * 4 + jj][c];
#pragma unroll
                for (int ii = 0; ii < 4; ii++)
#pragma unroll
                    for (int jj = 0; jj < 4; jj++) acc[ii][jj] += a[ii] * b[jj];
            }
#pragma unroll
            for (int ii = 0; ii < 4; ii++)
#pragma unroll
                for (int jj = 0; jj < 4; jj++)
                    g_L[(size_t)(r0 + ty * 4 + ii) * M_IND + o + tx * 4 + jj] = acc[ii][jj];
            __syncthreads();
        }
        gbar(sense);

        // syrk phase (+ fused diag factor for k+1 on CTA 0)
        if (bid == 0) {
            int bi = k + 1;
            for (int e = tid; e < BS * BS; e += 256) {
                int i = e / BS, j = e % BS;
                SB[i][j] = g_L[(size_t)(bi * BS + i) * M_IND + o + j];  // panel bi
            }
            __syncthreads();
            float acc[4][4];
#pragma unroll
            for (int ii = 0; ii < 4; ii++)
#pragma unroll
                for (int jj = 0; jj < 4; jj++)
                    acc[ii][jj] = g_L[(size_t)(bi * BS + ty * 4 + ii) * M_IND + bi * BS + tx * 4 + jj];
            for (int c = 0; c < BS; c++) {
                float a[4], b[4];
#pragma unroll
                for (int ii = 0; ii < 4; ii++) a[ii] = SB[ty * 4 + ii][c];
#pragma unroll
                for (int jj = 0; jj < 4; jj++) b[jj] = SB[tx * 4 + jj][c];
#pragma unroll
                for (int ii = 0; ii < 4; ii++)
#pragma unroll
                    for (int jj = 0; jj < 4; jj++) acc[ii][jj] -= a[ii] * b[jj];
            }
            __syncthreads();
#pragma unroll
            for (int ii = 0; ii < 4; ii++)
#pragma unroll
                for (int jj = 0; jj < 4; jj++)
                    SA[ty * 4 + ii][tx * 4 + jj] = acc[ii][jj];
            __syncthreads();
            factor_inverse(SA, SB, k + 1);
        } else {
            int ntile = t * (t + 1) / 2;
            for (int x = bid; x < ntile; x += NBLK - 1) {
                int r = 0;
                while ((r + 1) * (r + 2) / 2 <= x) r++;
                int c = x - r * (r + 1) / 2;
                int bi = k + 1 + r, bj = k + 1 + c;
                for (int e = tid; e < BS * BS; e += 256) {
                    int i = e / BS, j = e % BS;
                    SA[i][j] = g_L[(size_t)(bi * BS + i) * M_IND + o + j];
                    SB[i][j] = g_L[(size_t)(bj * BS + i) * M_IND + o + j];
                }
                __syncthreads();
                float acc[4][4];
#pragma unroll
                for (int ii = 0; ii < 4; ii++)
#pragma unroll
                    for (int jj = 0; jj < 4; jj++)
                        acc[ii][jj] = g_L[(size_t)(bi * BS + ty * 4 + ii) * M_IND + bj * BS + tx * 4 + jj];
                for (int cc = 0; cc < BS; cc++) {
                    float a[4], b[4];
#pragma unroll
                    for (int ii = 0; ii < 4; ii++) a[ii] = SA[ty * 4 + ii][cc];
#pragma unroll
                    for (int jj = 0; jj < 4; jj++) b[jj] = SB[tx * 4 + jj][cc];
#pragma unroll
                    for (int ii = 0; ii < 4; ii++)
#pragma unroll
                        for (int jj = 0; jj < 4; jj++) acc[ii][jj] -= a[ii] * b[jj];
                }
#pragma unroll
                for (int ii = 0; ii < 4; ii++)
#pragma unroll
                    for (int jj = 0; jj < 4; jj++)
                        g_L[(size_t)(bi * BS + ty * 4 + ii) * M_IND + bj * BS + tx * 4 + jj] = acc[ii][jj];
                __syncthreads();
            }
        }
        gbar(sense);
    }

    // winit: W = blockdiag(Zd)
    for (int idx = gthread; idx < M_IND * M_IND; idx += NBLK * 256) {
        int r = idx / M_IND, c = idx % M_IND;
        float v = 0.f;
        if (r / BS == c / BS)
            v = g_Zd[(r / BS) * BS * BS + (r % BS) * BS + (c % BS)];
        g_W[idx] = v;
    }
    gbar(sense);

    // recursive doubling: W21 = -W22 (L21 W11)
    for (int l = 0; l < 4; l++) {
        int s = 64 << l, tt = 1 << l, pairs = 8 >> l;
        int tiles = pairs * tt * tt;

        // phase A: tmp = L21 @ W11
        for (int x = bid; x < tiles; x += NBLK) {
            int p = x / (tt * tt), rem = x % (tt * tt), tr = rem / tt, tc = rem % tt;
            int base = p * 2 * s;
            float acc[4][4] = {};
            for (int k0 = tc * BS; k0 < s; k0 += BS) {       // W11 lower: skip upper chunks
                for (int e = tid; e < BS * BS; e += 256) {
                    int i = e / BS, j = e % BS;
                    SA[i][j] = g_L[(size_t)(base + s + tr * BS + i) * M_IND + base + k0 + j];
                    SB[i][j] = g_W[(size_t)(base + k0 + i) * M_IND + base + tc * BS + j];
                }
                __syncthreads();
                for (int c = 0; c < BS; c++) {
                    float a[4], b[4];
#pragma unroll
                    for (int ii = 0; ii < 4; ii++) a[ii] = SA[ty * 4 + ii][c];
#pragma unroll
                    for (int jj = 0; jj < 4; jj++) b[jj] = SB[c][tx * 4 + jj];
#pragma unroll
                    for (int ii = 0; ii < 4; ii++)
#pragma unroll
                        for (int jj = 0; jj < 4; jj++) acc[ii][jj] += a[ii] * b[jj];
                }
                __syncthreads();
            }
#pragma unroll
            for (int ii = 0; ii < 4; ii++)
#pragma unroll
                for (int jj = 0; jj < 4; jj++)
                    g_tmp[(size_t)p * s * s + (tr * BS + ty * 4 + ii) * s + tc * BS + tx * 4 + jj]
                        = acc[ii][jj];
            __syncthreads();
        }
        gbar(sense);

        // phase B: W21 = -W22 @ tmp
        for (int x = bid; x < tiles; x += NBLK) {
            int p = x / (tt * tt), rem = x % (tt * tt), tr = rem / tt, tc = rem % tt;
            int base = p * 2 * s;
            float acc[4][4] = {};
            for (int k0 = 0; k0 <= tr * BS; k0 += BS) {      // W22 lower: skip upper chunks
                for (int e = tid; e < BS * BS; e += 256) {
                    int i = e / BS, j = e % BS;
                    SA[i][j] = g_W[(size_t)(base + s + tr * BS + i) * M_IND + base + s + k0 + j];
                    SB[i][j] = g_tmp[(size_t)p * s * s + (k0 + i) * s + tc * BS + j];
                }
                __syncthreads();
                for (int c = 0; c < BS; c++) {
                    float a[4], b[4];
#pragma unroll
                    for (int ii = 0; ii < 4; ii++) a[ii] = SA[ty * 4 + ii][c];
#pragma unroll
                    for (int jj = 0; jj < 4; jj++) b[jj] = SB[c][tx * 4 + jj];
#pragma unroll
                    for (int ii = 0; ii < 4; ii++)
#pragma unroll
                        for (int jj = 0; jj < 4; jj++) acc[ii][jj] += a[ii] * b[jj];
                }
                __syncthreads();
            }
#pragma unroll
            for (int ii = 0; ii < 4; ii++)
#pragma unroll
                for (int jj = 0; jj < 4; jj++)
                    g_W[(size_t)(base + s + tr * BS + ty * 4 + ii) * M_IND + base + tc * BS + tx * 4 + jj]
                        = -acc[ii][jj];
            __syncthreads();
        }
        gbar(sense);
    }

    // a1 = W qu, a2 = W chole (one warp per row)
    int wid = gthread / 32, lane = tid % 32;
    for (int r = wid; r < M_IND; r += NBLK * 8) {
        float s1 = 0.f, s2 = 0.f;
        for (int c = lane; c <= r; c += 32) {
            float w = g_W[(size_t)r * M_IND + c];
            s1 += w * qu[c];
            s2 += w * ch[c];
        }
#pragma unroll
        for (int off = 16; off; off >>= 1) {
            s1 += __shfl_down_sync(0xffffffff, s1, off);
            s2 += __shfl_down_sync(0xffffffff, s2, off);
        }
        if (lane == 0) { g_a1[r] = s1; g_a2[r] = s2; }
    }
}

// ---------------------------------------------------------------------------
// init_S: S[m][n] = k(Xte_n, xm_m); padding columns = 0
// ---------------------------------------------------------------------------
__global__ void init_S(const float* __restrict__ Xte, const float* __restrict__ ls,
                       const float* __restrict__ sv) {
    __shared__ float Xs[64][D_DIM + 1];
    __shared__ float Ms[32][D_DIM + 1];
    int n0 = blockIdx.x * 64, m0 = blockIdx.y * 32;
    int tid = threadIdx.x;

    for (int e = tid; e < 64 * D_DIM; e += 256) {
        int i = e / D_DIM, d = e % D_DIM;
        int n = n0 + i;
        float il = 1.f / (fabsf(ls[d]) + EPSV);
        Xs[i][d] = (n < N_TE) ? Xte[n * D_DIM + d] * il : 0.f;
    }
    for (int e = tid; e < 32 * D_DIM; e += 256) {
        int i = e / D_DIM, d = e % D_DIM;
        Ms[i][d] = g_xs[(m0 + i) * D_DIM + d];
    }
    __syncthreads();

    float svv = fabsf(sv[0]);
    int tx = tid % 64, ty = tid / 64;
    int n = n0 + tx;
#pragma unroll
    for (int mi = 0; mi < 8; mi++) {
        int ml = ty * 8 + mi, m = m0 + ml;
        float outv = 0.f;
        if (n < N_TE) {
            float d2 = 0.f;
#pragma unroll
            for (int d = 0; d < D_DIM; d++) {
                float diff = Xs[tx][d] - Ms[ml][d];
                d2 += diff * diff;
            }
            outv = svv * __expf(-0.5f * d2);
        }
        g_S[(size_t)m * SW + n] = outv;
    }
}

// ---------------------------------------------------------------------------
// Fused GEMM + epilogue: for each (mb, n-block): T = W[mb rows] @ S, then
// partial q = sum T^2, mm = sum T*a1, vv = sum T*a2 reduced within CTA.
// ---------------------------------------------------------------------------
__global__ void __launch_bounds__(256) gemm_S() {
    __shared__ float Wsm[16][132];
    __shared__ float Ksm[16][132];
    __shared__ float Red[16][132];
    int tid = threadIdx.x;
    int n0 = blockIdx.x * 128;
    int mb = 7 - (int)blockIdx.y;       // heavy row-blocks first
    int m0 = mb * 128;
    int KM = m0 + 128;
    int tx = tid % 16, ty = tid / 16;
    int lm = tid / 2, lk = (tid % 2) * 8;
    int kr = tid / 16, kc = (tid % 16) * 8;

    const float* Wp = &g_W[(size_t)(m0 + lm) * M_IND + lk];
    float acc[8][8] = {};

    // prologue load k0 = 0
    float4 wa = *(const float4*)(Wp);
    float4 wb = *(const float4*)(Wp + 4);
    float4 ka = *(const float4*)&g_S[(size_t)kr * SW + n0 + kc];
    float4 kb = *(const float4*)&g_S[(size_t)kr * SW + n0 + kc + 4];

    for (int k0 = 0; k0 < KM; k0 += 16) {
        Wsm[lk + 0][lm] = wa.x; Wsm[lk + 1][lm] = wa.y;
        Wsm[lk + 2][lm] = wa.z; Wsm[lk + 3][lm] = wa.w;
        Wsm[lk + 4][lm] = wb.x; Wsm[lk + 5][lm] = wb.y;
        Wsm[lk + 6][lm] = wb.z; Wsm[lk + 7][lm] = wb.w;
        *(float4*)&Ksm[kr][kc]     = ka;
        *(float4*)&Ksm[kr][kc + 4] = kb;
        __syncthreads();

        int kn = k0 + 16;
        if (kn < KM) {
            wa = *(const float4*)(Wp + kn);
            wb = *(const float4*)(Wp + kn + 4);
            ka = *(const float4*)&g_S[(size_t)(kn + kr) * SW + n0 + kc];
            kb = *(const float4*)&g_S[(size_t)(kn + kr) * SW + n0 + kc + 4];
        }

#pragma unroll
        for (int kk = 0; kk < 16; kk++) {
            float4 a0 = *(const float4*)&Wsm[kk][ty * 8];
            float4 a1 = *(const float4*)&Wsm[kk][ty * 8 + 4];
            float4 b0 = *(const float4*)&Ksm[kk][tx * 8];
            float4 b1 = *(const float4*)&Ksm[kk][tx * 8 + 4];
            float a[8] = {a0.x, a0.y, a0.z, a0.w, a1.x, a1.y, a1.z, a1.w};
            float b[8] = {b0.x, b0.y, b0.z, b0.w, b1.x, b1.y, b1.z, b1.w};
#pragma unroll
            for (int ii = 0; ii < 8; ii++)
#pragma unroll
                for (int jj = 0; jj < 8; jj++)
                    acc[ii][jj] += a[ii] * b[jj];
        }
        __syncthreads();
    }

    // epilogue: CTA-level partial reductions, no S2 store
    float a1v[8], a2v[8];
#pragma unroll
    for (int ii = 0; ii < 8; ii++) {
        a1v[ii] = g_a1[m0 + ty * 8 + ii];
        a2v[ii] = g_a2[m0 + ty * 8 + ii];
    }

    // q
#pragma unroll
    for (int jj = 0; jj < 8; jj++) {
        float s = 0.f;
#pragma unroll
        for (int ii = 0; ii < 8; ii++) s += acc[ii][jj] * acc[ii][jj];
        Red[ty][tx * 8 + jj] = s;
    }
    __syncthreads();
    if (tid < 128) {
        float s = 0.f;
#pragma unroll
        for (int r = 0; r < 16; r++) s += Red[r][tid];
        g_q[mb * SW + n0 + tid] = s;
    }
    __syncthreads();

    // mm
#pragma unroll
    for (int jj = 0; jj < 8; jj++) {
        float s = 0.f;
#pragma unroll
        for (int ii = 0; ii < 8; ii++) s += acc[ii][jj] * a1v[ii];
        Red[ty][tx * 8 + jj] = s;
    }
    __syncthreads();
    if (tid < 128) {
        float s = 0.f;
#pragma unroll
        for (int r = 0; r < 16; r++) s += Red[r][tid];
        g_mm[mb * SW + n0 + tid] = s;
    }
    __syncthreads();

    // vv
#pragma unroll
    for (int jj = 0; jj < 8; jj++) {
        float s = 0.f;
#pragma unroll
        for (int ii = 0; ii < 8; ii++) s += acc[ii][jj] * a2v[ii];
        Red[ty][tx * 8 + jj] = s;
    }
    __syncthreads();
    if (tid < 128) {
        float s = 0.f;
#pragma unroll
        for (int r = 0; r < 16; r++) s += Red[r][tid];
        g_vv[mb * SW + n0 + tid] = s;
    }
}

// ---------------------------------------------------------------------------
// Final reduce over the 8 mb partials
// ---------------------------------------------------------------------------
__global__ void reduce_out(float* __restrict__ out, const float* __restrict__ sv) {
    int n = blockIdx.x * 256 + threadIdx.x;
    if (n >= N_TE) return;
    float q = 0.f, mm = 0.f, vv = 0.f;
#pragma unroll
    for (int mb = 0; mb < 8; mb++) {
        q  += g_q[mb * SW + n];
        mm += g_mm[mb * SW + n];
        vv += g_vv[mb * SW + n];
    }
    float svv = fabsf(sv[0]);
    out[n] = mm;
    out[N_TE + n] = svv - q + vv * vv;
}

// ---------------------------------------------------------------------------
extern "C" void kernel_launch(void* const* d_in, const int* in_sizes, int n_in,
                              void* d_out, int out_size) {
    const float* Xte = (const float*)d_in[0];
    const float* xm  = (const float*)d_in[1];
    const float* qu  = (const float*)d_in[2];
    const float* ch  = (const float*)d_in[3];
    const float* ls  = (const float*)d_in[4];
    const float* sv  = (const float*)d_in[5];
    float* out = (float*)d_out;

    fact_kernel<<<NBLK, 256>>>(xm, qu, ch, ls, sv);
    init_S<<<dim3(SW / 64, M_IND / 32), 256>>>(Xte, ls, sv);
    gemm_S<<<dim3(SW / 128, 8), 256>>>();
    reduce_out<<<(N_TE + 255) / 256, 256>>>(out, sv);
}

// round 5
// speedup vs baseline: 1.7344x; 1.2287x over previous
#include <cuda_runtime.h>
#include <cuda_bf16.h>
#include <math.h>
#include <stdint.h>

// Problem constants (fixed by setup_inputs)
#define N_TE   20000
#define M_IND  1024
#define D_DIM  16
#define BS     64
#define NB     16
#define SW     20096          // 157*128 padded width
#define JITTER 1e-3f
#define EPSV   1e-9f
#define NBLK   120            // persistent grid for fact kernel

// ---- PTX helpers (sm_100-safe: mma.sync / ldmatrix / cp.async) ------------
__device__ __forceinline__ uint32_t smem_to_u32(const void* p) {
    uint32_t a;
    asm("{ .reg .u64 t; cvta.to.shared.u64 t, %1; cvt.u32.u64 %0, t; }" : "=r"(a) : "l"(p));
    return a;
}
#define CPA(dst, src) \
    asm volatile("cp.async.cg.shared.global [%0], [%1], 16;" :: "r"(dst), "l"(src))
#define CPC() asm volatile("cp.async.commit_group;" ::: "memory")
#define CPW0() asm volatile("cp.async.wait_group 0;" ::: "memory")
#define CPW1() asm volatile("cp.async.wait_group 1;" ::: "memory")
#define LDSM4(R, addr) \
    asm volatile("ldmatrix.sync.aligned.m8n8.x4.shared.b16 {%0,%1,%2,%3}, [%4];" \
        : "=r"((R)[0]), "=r"((R)[1]), "=r"((R)[2]), "=r"((R)[3]) : "r"(addr))
#define MMA16816(acc, a, b0_, b1_) \
    asm volatile("mma.sync.aligned.m16n8k16.row.col.f32.bf16.bf16.f32 " \
        "{%0,%1,%2,%3}, {%4,%5,%6,%7}, {%8,%9}, {%0,%1,%2,%3};" \
        : "+f"((acc)[0]), "+f"((acc)[1]), "+f"((acc)[2]), "+f"((acc)[3]) \
        : "r"((a)[0]), "r"((a)[1]), "r"((a)[2]), "r"((a)[3]), "r"(b0_), "r"(b1_))

// ---- scratch (allocation-free: __device__ globals) ------------------------
__device__ float g_L[M_IND * M_IND];
__device__ float g_W[M_IND * M_IND];
__device__ float g_Zd[NB * BS * BS];
__device__ float g_tmp[512 * 512];
__device__ float g_xs[M_IND * D_DIM];
__device__ float g_nm[M_IND];
__device__ float g_a1[M_IND];
__device__ float g_a2[M_IND];
__device__ float g_q[8 * SW];
__device__ float g_mm[8 * SW];
__device__ float g_vv[8 * SW];
__device__ __nv_bfloat16 g_Whi[M_IND * M_IND];
__device__ __nv_bfloat16 g_Wlo[M_IND * M_IND];
__device__ __nv_bfloat16 g_Shi[(size_t)SW * M_IND];   // [n][k] layout
__device__ __nv_bfloat16 g_Slo[(size_t)SW * M_IND];
__device__ unsigned g_cnt = 0;
__device__ volatile unsigned g_epoch = 0;

// ---------------------------------------------------------------------------
// Software grid barrier (monotonic epoch: safe across graph replays)
// ---------------------------------------------------------------------------
__device__ __forceinline__ void gbar(unsigned& sense) {
    __syncthreads();
    if (threadIdx.x == 0) {
        unsigned target = sense + 1;
        __threadfence();
        unsigned old = atomicAdd(&g_cnt, 1u);
        if (old == NBLK - 1) {
            atomicExch(&g_cnt, 0u);
            __threadfence();
            g_epoch = target;
        } else {
            while (g_epoch < target) { }
            __threadfence();
        }
    }
    __syncthreads();
    sense += 1;
}

// ---------------------------------------------------------------------------
// Diagonal 64x64 block: deferred-scale Cholesky factor + triangular inverse
// ---------------------------------------------------------------------------
__device__ void factor_inverse(float (&Lb)[BS][BS + 1], float (&Zb)[BS][BS + 1], int kout) {
    int tid = threadIdx.x, tx = tid % 16, ty = tid / 16;
    for (int e = tid; e < BS * BS; e += 256)
        Zb[e / BS][e % BS] = (e / BS == e % BS) ? 1.f : 0.f;
    __syncthreads();

    for (int j = 0; j < BS - 1; j++) {
        float inv = 1.f / Lb[j][j];
        for (int r = j + 1 + ty; r < BS; r += 16) {
            float lrj = Lb[r][j] * inv;
            for (int c = j + 1 + tx; c <= r; c += 16)
                Lb[r][c] -= lrj * Lb[c][j];
        }
        __syncthreads();
    }
    float vals[16];
    int q = 0;
    for (int e = tid; e < BS * BS; e += 256, q++) {
        int r = e / BS, c = e % BS;
        float v = Lb[r][c];
        if (c < r)       v *= rsqrtf(Lb[c][c]);
        else if (c == r) v = sqrtf(v);
        vals[q] = v;
    }
    __syncthreads();
    q = 0;
    for (int e = tid; e < BS * BS; e += 256, q++)
        Lb[e / BS][e % BS] = vals[q];
    __syncthreads();

    for (int i = 0; i < BS; i++) {
        float inv = 1.f / Lb[i][i];
        for (int j = tid; j <= i; j += 256) Zb[i][j] *= inv;
        __syncthreads();
        for (int r = i + 1 + ty; r < BS; r += 16) {
            float lri = Lb[r][i];
            for (int j = tx; j <= i; j += 16)
                Zb[r][j] -= lri * Zb[i][j];
        }
        __syncthreads();
    }
    for (int e = tid; e < BS * BS; e += 256)
        g_Zd[kout * BS * BS + e] = Zb[e / BS][e % BS];
    __syncthreads();
}

// ---------------------------------------------------------------------------
// Persistent kernel: K_mm -> Cholesky(L, Zd) -> W = L^{-1} -> a1, a2
// ---------------------------------------------------------------------------
__global__ void __launch_bounds__(256) fact_kernel(const float* __restrict__ xm,
                                                   const float* __restrict__ qu,
                                                   const float* __restrict__ ch,
                                                   const float* __restrict__ ls,
                                                   const float* __restrict__ sv) {
    __shared__ float SA[BS][BS + 1];
    __shared__ float SB[BS][BS + 1];
    __shared__ unsigned s0;
    int tid = threadIdx.x, bid = blockIdx.x;
    if (tid == 0) s0 = g_epoch;
    __syncthreads();
    unsigned sense = s0;

    int gthread = bid * 256 + tid;
    int tx = tid % 16, ty = tid / 16;

    for (int m = gthread; m < M_IND; m += NBLK * 256) {
        float nrm = 0.f;
#pragma unroll
        for (int d = 0; d < D_DIM; d++) {
            float il = 1.f / (fabsf(ls[d]) + EPSV);
            float v = xm[m * D_DIM + d] * il;
            g_xs[m * D_DIM + d] = v;
            nrm += v * v;
        }
        g_nm[m] = nrm;
    }
    gbar(sense);

    float svv = fabsf(sv[0]);
    for (int idx = gthread; idx < M_IND * M_IND; idx += NBLK * 256) {
        int r = idx / M_IND, c = idx % M_IND;
        float dot = 0.f;
#pragma unroll
        for (int d = 0; d < D_DIM; d++)
            dot += g_xs[r * D_DIM + d] * g_xs[c * D_DIM + d];
        float d2 = fmaxf(g_nm[r] + g_nm[c] - 2.f * dot, 0.f);
        float v = svv * __expf(-0.5f * d2);
        if (r == c) v += JITTER;
        g_L[idx] = v;
    }
    gbar(sense);

    if (bid == 0) {
        for (int e = tid; e < BS * BS; e += 256)
            SA[e / BS][e % BS] = g_L[(size_t)(e / BS) * M_IND + (e % BS)];
        __syncthreads();
        factor_inverse(SA, SB, 0);
    }
    gbar(sense);

    for (int k = 0; k < NB - 1; k++) {
        int o = k * BS, t = NB - 1 - k;

        for (int pidx = bid; pidx < t; pidx += NBLK) {
            int r0 = o + BS + pidx * BS;
            for (int e = tid; e < BS * BS; e += 256) {
                int i = e / BS, j = e % BS;
                SA[i][j] = g_L[(size_t)(r0 + i) * M_IND + o + j];
                SB[i][j] = g_Zd[k * BS * BS + e];
            }
            __syncthreads();
            float acc[4][4] = {};
            for (int c = 0; c < BS; c++) {
                float a[4], b[4];
#pragma unroll
                for (int ii = 0; ii < 4; ii++) a[ii] = SA[ty * 4 + ii][c];
#pragma unroll
                for (int jj = 0; jj < 4; jj++) b[jj] = SB[tx * 4 + jj][c];
#pragma unroll
                for (int ii = 0; ii < 4; ii++)
#pragma unroll
                    for (int jj = 0; jj < 4; jj++) acc[ii][jj] += a[ii] * b[jj];
            }
#pragma unroll
            for (int ii = 0; ii < 4; ii++)
#pragma unroll
                for (int jj = 0; jj < 4; jj++)
                    g_L[(size_t)(r0 + ty * 4 + ii) * M_IND + o + tx * 4 + jj] = acc[ii][jj];
            __syncthreads();
        }
        gbar(sense);

        if (bid == 0) {
            int bi = k + 1;
            for (int e = tid; e < BS * BS; e += 256) {
                int i = e / BS, j = e % BS;
                SB[i][j] = g_L[(size_t)(bi * BS + i) * M_IND + o + j];
            }
            __syncthreads();
            float acc[4][4];
#pragma unroll
            for (int ii = 0; ii < 4; ii++)
#pragma unroll
                for (int jj = 0; jj < 4; jj++)
                    acc[ii][jj] = g_L[(size_t)(bi * BS + ty * 4 + ii) * M_IND + bi * BS + tx * 4 + jj];
            for (int c = 0; c < BS; c++) {
                float a[4], b[4];
#pragma unroll
                for (int ii = 0; ii < 4; ii++) a[ii] = SB[ty * 4 + ii][c];
#pragma unroll
                for (int jj = 0; jj < 4; jj++) b[jj] = SB[tx * 4 + jj][c];
#pragma unroll
                for (int ii = 0; ii < 4; ii++)
#pragma unroll
                    for (int jj = 0; jj < 4; jj++) acc[ii][jj] -= a[ii] * b[jj];
            }
            __syncthreads();
#pragma unroll
            for (int ii = 0; ii < 4; ii++)
#pragma unroll
                for (int jj = 0; jj < 4; jj++)
                    SA[ty * 4 + ii][tx * 4 + jj] = acc[ii][jj];
            __syncthreads();
            factor_inverse(SA, SB, k + 1);
        } else {
            int ntile = t * (t + 1) / 2;
            for (int x = bid; x < ntile; x += NBLK - 1) {
                int r = 0;
                while ((r + 1) * (r + 2) / 2 <= x) r++;
                int c = x - r * (r + 1) / 2;
                int bi = k + 1 + r, bj = k + 1 + c;
                for (int e = tid; e < BS * BS; e += 256) {
                    int i = e / BS, j = e % BS;
                    SA[i][j] = g_L[(size_t)(bi * BS + i) * M_IND + o + j];
                    SB[i][j] = g_L[(size_t)(bj * BS + i) * M_IND + o + j];
                }
                __syncthreads();
                float acc[4][4];
#pragma unroll
                for (int ii = 0; ii < 4; ii++)
#pragma unroll
                    for (int jj = 0; jj < 4; jj++)
                        acc[ii][jj] = g_L[(size_t)(bi * BS + ty * 4 + ii) * M_IND + bj * BS + tx * 4 + jj];
                for (int cc = 0; cc < BS; cc++) {
                    float a[4], b[4];
#pragma unroll
                    for (int ii = 0; ii < 4; ii++) a[ii] = SA[ty * 4 + ii][cc];
#pragma unroll
                    for (int jj = 0; jj < 4; jj++) b[jj] = SB[tx * 4 + jj][cc];
#pragma unroll
                    for (int ii = 0; ii < 4; ii++)
#pragma unroll
                        for (int jj = 0; jj < 4; jj++) acc[ii][jj] -= a[ii] * b[jj];
                }
#pragma unroll
                for (int ii = 0; ii < 4; ii++)
#pragma unroll
                    for (int jj = 0; jj < 4; jj++)
                        g_L[(size_t)(bi * BS + ty * 4 + ii) * M_IND + bj * BS + tx * 4 + jj] = acc[ii][jj];
                __syncthreads();
            }
        }
        gbar(sense);
    }

    for (int idx = gthread; idx < M_IND * M_IND; idx += NBLK * 256) {
        int r = idx / M_IND, c = idx % M_IND;
        float v = 0.f;
        if (r / BS == c / BS)
            v = g_Zd[(r / BS) * BS * BS + (r % BS) * BS + (c % BS)];
        g_W[idx] = v;
    }
    gbar(sense);

    for (int l = 0; l < 4; l++) {
        int s = 64 << l, tt = 1 << l, pairs = 8 >> l;
        int tiles = pairs * tt * tt;

        for (int x = bid; x < tiles; x += NBLK) {
            int p = x / (tt * tt), rem = x % (tt * tt), tr = rem / tt, tc = rem % tt;
            int base = p * 2 * s;
            float acc[4][4] = {};
            for (int k0 = tc * BS; k0 < s; k0 += BS) {
                for (int e = tid; e < BS * BS; e += 256) {
                    int i = e / BS, j = e % BS;
                    SA[i][j] = g_L[(size_t)(base + s + tr * BS + i) * M_IND + base + k0 + j];
                    SB[i][j] = g_W[(size_t)(base + k0 + i) * M_IND + base + tc * BS + j];
                }
                __syncthreads();
                for (int c = 0; c < BS; c++) {
                    float a[4], b[4];
#pragma unroll
                    for (int ii = 0; ii < 4; ii++) a[ii] = SA[ty * 4 + ii][c];
#pragma unroll
                    for (int jj = 0; jj < 4; jj++) b[jj] = SB[c][tx * 4 + jj];
#pragma unroll
                    for (int ii = 0; ii < 4; ii++)
#pragma unroll
                        for (int jj = 0; jj < 4; jj++) acc[ii][jj] += a[ii] * b[jj];
                }
                __syncthreads();
            }
#pragma unroll
            for (int ii = 0; ii < 4; ii++)
#pragma unroll
                for (int jj = 0; jj < 4; jj++)
                    g_tmp[(size_t)p * s * s + (tr * BS + ty * 4 + ii) * s + tc * BS + tx * 4 + jj]
                        = acc[ii][jj];
            __syncthreads();
        }
        gbar(sense);

        for (int x = bid; x < tiles; x += NBLK) {
            int p = x / (tt * tt), rem = x % (tt * tt), tr = rem / tt, tc = rem % tt;
            int base = p * 2 * s;
            float acc[4][4] = {};
            for (int k0 = 0; k0 <= tr * BS; k0 += BS) {
                for (int e = tid; e < BS * BS; e += 256) {
                    int i = e / BS, j = e % BS;
                    SA[i][j] = g_W[(size_t)(base + s + tr * BS + i) * M_IND + base + s + k0 + j];
                    SB[i][j] = g_tmp[(size_t)p * s * s + (k0 + i) * s + tc * BS + j];
                }
                __syncthreads();
                for (int c = 0; c < BS; c++) {
                    float a[4], b[4];
#pragma unroll
                    for (int ii = 0; ii < 4; ii++) a[ii] = SA[ty * 4 + ii][c];
#pragma unroll
                    for (int jj = 0; jj < 4; jj++) b[jj] = SB[c][tx * 4 + jj];
#pragma unroll
                    for (int ii = 0; ii < 4; ii++)
#pragma unroll
                        for (int jj = 0; jj < 4; jj++) acc[ii][jj] += a[ii] * b[jj];
                }
                __syncthreads();
            }
#pragma unroll
            for (int ii = 0; ii < 4; ii++)
#pragma unroll
                for (int jj = 0; jj < 4; jj++)
                    g_W[(size_t)(base + s + tr * BS + ty * 4 + ii) * M_IND + base + tc * BS + tx * 4 + jj]
                        = -acc[ii][jj];
            __syncthreads();
        }
        gbar(sense);
    }

    // a1 = W qu, a2 = W chole
    int wid = gthread / 32, lane = tid % 32;
    for (int r = wid; r < M_IND; r += NBLK * 8) {
        float s1 = 0.f, s2 = 0.f;
        for (int c = lane; c <= r; c += 32) {
            float w = g_W[(size_t)r * M_IND + c];
            s1 += w * qu[c];
            s2 += w * ch[c];
        }
#pragma unroll
        for (int off = 16; off; off >>= 1) {
            s1 += __shfl_down_sync(0xffffffff, s1, off);
            s2 += __shfl_down_sync(0xffffffff, s2, off);
        }
        if (lane == 0) { g_a1[r] = s1; g_a2[r] = s2; }
    }
}

// ---------------------------------------------------------------------------
// W -> bf16 hi/lo split
// ---------------------------------------------------------------------------
__global__ void wconv() {
    int idx = blockIdx.x * 256 + threadIdx.x;
    if (idx >= M_IND * M_IND) return;
    float w = g_W[idx];
    __nv_bfloat16 h = __float2bfloat16(w);
    g_Whi[idx] = h;
    g_Wlo[idx] = __float2bfloat16(w - __bfloat162float(h));
}

// ---------------------------------------------------------------------------
// init_S: Shi/Slo[n][k] = bf16 split of k(Xte_n, xm_k); padding rows = 0
// ---------------------------------------------------------------------------
__global__ void init_S(const float* __restrict__ Xte, const float* __restrict__ ls,
                       const float* __restrict__ sv) {
    __shared__ float Xs[64][D_DIM + 1];
    __shared__ float Ms[32][D_DIM + 1];
    int n0 = blockIdx.x * 64, m0 = blockIdx.y * 32;
    int tid = threadIdx.x;

    for (int e = tid; e < 64 * D_DIM; e += 256) {
        int i = e / D_DIM, d = e % D_DIM;
        int n = n0 + i;
        float il = 1.f / (fabsf(ls[d]) + EPSV);
        Xs[i][d] = (n < N_TE) ? Xte[n * D_DIM + d] * il : 0.f;
    }
    for (int e = tid; e < 32 * D_DIM; e += 256) {
        int i = e / D_DIM, d = e % D_DIM;
        Ms[i][d] = g_xs[(m0 + i) * D_DIM + d];
    }
    __syncthreads();

    float svv = fabsf(sv[0]);
    int tx = tid % 64, ty = tid / 64;
    int n = n0 + tx;
    __align__(16) __nv_bfloat16 h8[8];
    __align__(16) __nv_bfloat16 l8[8];
#pragma unroll
    for (int mi = 0; mi < 8; mi++) {
        int ml = ty * 8 + mi;
        float outv = 0.f;
        if (n < N_TE) {
            float d2 = 0.f;
#pragma unroll
            for (int d = 0; d < D_DIM; d++) {
                float diff = Xs[tx][d] - Ms[ml][d];
                d2 += diff * diff;
            }
            outv = svv * __expf(-0.5f * d2);
        }
        __nv_bfloat16 h = __float2bfloat16(outv);
        h8[mi] = h;
        l8[mi] = __float2bfloat16(outv - __bfloat162float(h));
    }
    size_t off = (size_t)n * M_IND + m0 + ty * 8;
    *(uint4*)&g_Shi[off] = *(uint4*)h8;
    *(uint4*)&g_Slo[off] = *(uint4*)l8;
}

// ---------------------------------------------------------------------------
// Warp-MMA bf16 GEMM + fused epilogue.
//   CTA: D[128m x 128n] = Whi*Shi + Wlo*Shi + Whi*Slo over k in [0, m0+128)
//   8 warps (2m x 4n), warp tile 64x32, mma.sync m16n8k16.
//   Double-buffered cp.async smem: 4 tiles x 16KB per stage (SW128 swizzle).
// ---------------------------------------------------------------------------
#define STG_BYTES 65536
__global__ void __launch_bounds__(256) gemm_tc() {
    extern __shared__ __align__(1024) char dsm[];
    __shared__ float Rq[8][32], Rm[8][32], Rv[8][32];
    __shared__ float a1s[128], a2s[128];

    const uint32_t sbase = smem_to_u32(dsm);
    int tid = threadIdx.x, wid = tid >> 5, lane = tid & 31;
    int n0 = blockIdx.x * 128;
    int mb = 7 - (int)blockIdx.y;
    int m0 = mb * 128;
    int nchunks = (m0 + 128) >> 6;

    if (tid < 128) { a1s[tid] = g_a1[m0 + tid]; a2s[tid] = g_a2[m0 + tid]; }

    // loader indices: 4 copies (one per tile) x 4 iterations of 256 threads
    int lrow = tid >> 1;                  // 0..127 (2 threads per row)
    // each thread handles chunks {c4, c4+1, c4+2, c4+3}? -> simpler: e-loop

    // ldmatrix per-thread bases
    int wm = (wid >> 2) * 64;             // warp m offset (0 or 64)
    int wn = (wid & 3) * 32;              // warp n offset
    int lrow16 = lane & 15, lhalf = lane >> 4;

    float acc[4][4][4];
#pragma unroll
    for (int i = 0; i < 4; i++)
#pragma unroll
        for (int j = 0; j < 4; j++)
#pragma unroll
            for (int r = 0; r < 4; r++) acc[i][j][r] = 0.f;

    // --- async load of chunk c into stage buffer ---
    auto issue = [&](int c) {
        int k0 = c << 6;
        uint32_t buf = sbase + (uint32_t)(c & 1) * STG_BYTES;
#pragma unroll
        for (int it = 0; it < 4; it++) {
            int e = tid + it * 256;       // 0..1023
            int row = e >> 3, ch = e & 7;
            uint32_t soff = (uint32_t)(row * 128 + ((ch ^ (row & 7)) << 4));
            const __nv_bfloat16* wsrc = &g_Whi[(size_t)(m0 + row) * M_IND + k0 + ch * 8];
            const __nv_bfloat16* ssrc = &g_Shi[(size_t)(n0 + row) * M_IND + k0 + ch * 8];
            CPA(buf + soff,         wsrc);
            CPA(buf + 16384 + soff, wsrc + (size_t)M_IND * M_IND);      // g_Wlo follows? NO
        }
    };
    (void)lrow;

    // NOTE: g_Wlo is a separate symbol; use explicit pointers instead of offset trick.
    // Re-implement issue without lambda-symbol hazards:
    for (int c = 0; c < nchunks + 1; c++) {
        if (c < nchunks) {
            int k0 = c << 6;
            uint32_t buf = sbase + (uint32_t)(c & 1) * STG_BYTES;
#pragma unroll
            for (int it = 0; it < 4; it++) {
                int e = tid + it * 256;
                int row = e >> 3, ch = e & 7;
                uint32_t soff = (uint32_t)(row * 128 + ((ch ^ (row & 7)) << 4));
                size_t wsrc = (size_t)(m0 + row) * M_IND + k0 + ch * 8;
                size_t ssrc = (size_t)(n0 + row) * M_IND + k0 + ch * 8;
                CPA(buf + soff,         &g_Whi[wsrc]);
                CPA(buf + 16384 + soff, &g_Wlo[wsrc]);
                CPA(buf + 32768 + soff, &g_Shi[ssrc]);
                CPA(buf + 49152 + soff, &g_Slo[ssrc]);
            }
            CPC();
        }
        if (c == 0) continue;            // nothing to compute yet

        // wait for chunk c-1 (keep at most the just-issued group in flight)
        if (c < nchunks) { CPW1(); } else { CPW0(); }
        __syncthreads();

        int cc = c - 1;
        uint32_t buf = sbase + (uint32_t)(cc & 1) * STG_BYTES;
        uint32_t WHIa = buf, WLOa = buf + 16384, SHIa = buf + 32768, SLOa = buf + 49152;

#pragma unroll
        for (int kk = 0; kk < 4; kk++) {
            uint32_t A[4][4], Bf[2][4];
            // B = Shi
#pragma unroll
            for (int j2 = 0; j2 < 2; j2++) {
                int row = wn + j2 * 16 + lrow16;
                int ch = kk * 2 + lhalf;
                LDSM4(Bf[j2], SHIa + (uint32_t)(row * 128 + ((ch ^ (row & 7)) << 4)));
            }
            // A = Whi
#pragma unroll
            for (int i = 0; i < 4; i++) {
                int row = wm + i * 16 + lrow16;
                int ch = kk * 2 + lhalf;
                LDSM4(A[i], WHIa + (uint32_t)(row * 128 + ((ch ^ (row & 7)) << 4)));
            }
#pragma unroll
            for (int i = 0; i < 4; i++)
#pragma unroll
                for (int j = 0; j < 4; j++)
                    MMA16816(acc[i][j], A[i], Bf[j >> 1][j & 1], Bf[j >> 1][(j & 1) + 2]);
            // B = Slo (A still Whi)
#pragma unroll
            for (int j2 = 0; j2 < 2; j2++) {
                int row = wn + j2 * 16 + lrow16;
                int ch = kk * 2 + lhalf;
                LDSM4(Bf[j2], SLOa + (uint32_t)(row * 128 + ((ch ^ (row & 7)) << 4)));
            }
#pragma unroll
            for (int i = 0; i < 4; i++)
#pragma unroll
                for (int j = 0; j < 4; j++)
                    MMA16816(acc[i][j], A[i], Bf[j >> 1][j & 1], Bf[j >> 1][(j & 1) + 2]);
            // A = Wlo, B = Shi again
#pragma unroll
            for (int i = 0; i < 4; i++) {
                int row = wm + i * 16 + lrow16;
                int ch = kk * 2 + lhalf;
                LDSM4(A[i], WLOa + (uint32_t)(row * 128 + ((ch ^ (row & 7)) << 4)));
            }
#pragma unroll
            for (int j2 = 0; j2 < 2; j2++) {
                int row = wn + j2 * 16 + lrow16;
                int ch = kk * 2 + lhalf;
                LDSM4(Bf[j2], SHIa + (uint32_t)(row * 128 + ((ch ^ (row & 7)) << 4)));
            }
#pragma unroll
            for (int i = 0; i < 4; i++)
#pragma unroll
                for (int j = 0; j < 4; j++)
                    MMA16816(acc[i][j], A[i], Bf[j >> 1][j & 1], Bf[j >> 1][(j & 1) + 2]);
        }
        __syncthreads();
    }

    // ---- fused epilogue: q/mm/vv partials ----
    float a1r[8], a2r[8];
#pragma unroll
    for (int i = 0; i < 4; i++)
#pragma unroll
        for (int rh = 0; rh < 2; rh++) {
            int row = wm + i * 16 + (lane >> 2) + rh * 8;
            a1r[i * 2 + rh] = a1s[row];
            a2r[i * 2 + rh] = a2s[row];
        }

    float pq[8], pm[8], pv[8];
#pragma unroll
    for (int j = 0; j < 4; j++)
#pragma unroll
        for (int cbit = 0; cbit < 2; cbit++) {
            float q = 0.f, m = 0.f, v = 0.f;
#pragma unroll
            for (int i = 0; i < 4; i++)
#pragma unroll
                for (int rh = 0; rh < 2; rh++) {
                    float x = acc[i][j][rh * 2 + cbit];
                    q += x * x;
                    m += x * a1r[i * 2 + rh];
                    v += x * a2r[i * 2 + rh];
                }
            pq[j * 2 + cbit] = q; pm[j * 2 + cbit] = m; pv[j * 2 + cbit] = v;
        }
#pragma unroll
    for (int off = 4; off <= 16; off <<= 1)
#pragma unroll
        for (int s = 0; s < 8; s++) {
            pq[s] += __shfl_xor_sync(0xffffffff, pq[s], off);
            pm[s] += __shfl_xor_sync(0xffffffff, pm[s], off);
            pv[s] += __shfl_xor_sync(0xffffffff, pv[s], off);
        }
    if (lane < 4) {
#pragma unroll
        for (int j = 0; j < 4; j++)
#pragma unroll
            for (int cbit = 0; cbit < 2; cbit++) {
                int col = j * 8 + lane * 2 + cbit;
                Rq[wid][col] = pq[j * 2 + cbit];
                Rm[wid][col] = pm[j * 2 + cbit];
                Rv[wid][col] = pv[j * 2 + cbit];
            }
    }
    __syncthreads();
    if (tid < 128) {
        int n = tid;
        int w = n >> 5, cl = n & 31;
        g_q[mb * SW + n0 + n]  = Rq[w][cl] + Rq[w + 4][cl];
        g_mm[mb * SW + n0 + n] = Rm[w][cl] + Rm[w + 4][cl];
        g_vv[mb * SW + n0 + n] = Rv[w][cl] + Rv[w + 4][cl];
    }
}

// ---------------------------------------------------------------------------
// Final reduce over the 8 mb partials
// ---------------------------------------------------------------------------
__global__ void reduce_out(float* __restrict__ out, const float* __restrict__ sv) {
    int n = blockIdx.x * 256 + threadIdx.x;
    if (n >= N_TE) return;
    float q = 0.f, mm = 0.f, vv = 0.f;
#pragma unroll
    for (int mb = 0; mb < 8; mb++) {
        q  += g_q[mb * SW + n];
        mm += g_mm[mb * SW + n];
        vv += g_vv[mb * SW + n];
    }
    float svv = fabsf(sv[0]);
    out[n] = mm;
    out[N_TE + n] = svv - q + vv * vv;
}

// ---------------------------------------------------------------------------
extern "C" void kernel_launch(void* const* d_in, const int* in_sizes, int n_in,
                              void* d_out, int out_size) {
    const float* Xte = (const float*)d_in[0];
    const float* xm  = (const float*)d_in[1];
    const float* qu  = (const float*)d_in[2];
    const float* ch  = (const float*)d_in[3];
    const float* ls  = (const float*)d_in[4];
    const float* sv  = (const float*)d_in[5];
    float* out = (float*)d_out;

    static bool attr_done = false;
    if (!attr_done) {
        cudaFuncSetAttribute(gemm_tc, cudaFuncAttributeMaxDynamicSharedMemorySize,
                             2 * STG_BYTES);
        attr_done = true;
    }

    fact_kernel<<<NBLK, 256>>>(xm, qu, ch, ls, sv);
    wconv<<<(M_IND * M_IND + 255) / 256, 256>>>();
    init_S<<<dim3(SW / 64, M_IND / 32), 256>>>(Xte, ls, sv);
    gemm_tc<<<dim3(SW / 128, 8), 256, 2 * STG_BYTES>>>();
    reduce_out<<<(N_TE + 255) / 256, 256>>>(out, sv);
}

// round 6
// speedup vs baseline: 2.2695x; 1.3085x over previous
#include <cuda_runtime.h>
#include <cuda_bf16.h>
#include <math.h>
#include <stdint.h>

// Problem constants (fixed by setup_inputs)
#define N_TE   20000
#define M_IND  1024
#define D_DIM  16
#define BS     64
#define NB     16
#define SW     20096          // 157*128 padded width
#define JITTER 1e-3f
#define EPSV   1e-9f
#define NBLK   120            // persistent grid for fact kernel

// ---- PTX helpers (sm_100-safe: mma.sync / ldmatrix / cp.async) ------------
__device__ __forceinline__ uint32_t smem_to_u32(const void* p) {
    uint32_t a;
    asm("{ .reg .u64 t; cvta.to.shared.u64 t, %1; cvt.u32.u64 %0, t; }" : "=r"(a) : "l"(p));
    return a;
}
#define CPA(dst, src) \
    asm volatile("cp.async.cg.shared.global [%0], [%1], 16;" :: "r"(dst), "l"(src))
#define CPC() asm volatile("cp.async.commit_group;" ::: "memory")
#define CPW0() asm volatile("cp.async.wait_group 0;" ::: "memory")
#define CPW1() asm volatile("cp.async.wait_group 1;" ::: "memory")
#define LDSM4(R, addr) \
    asm volatile("ldmatrix.sync.aligned.m8n8.x4.shared.b16 {%0,%1,%2,%3}, [%4];" \
        : "=r"((R)[0]), "=r"((R)[1]), "=r"((R)[2]), "=r"((R)[3]) : "r"(addr))
#define MMA16816(acc, a, b0_, b1_) \
    asm volatile("mma.sync.aligned.m16n8k16.row.col.f32.bf16.bf16.f32 " \
        "{%0,%1,%2,%3}, {%4,%5,%6,%7}, {%8,%9}, {%0,%1,%2,%3};" \
        : "+f"((acc)[0]), "+f"((acc)[1]), "+f"((acc)[2]), "+f"((acc)[3]) \
        : "r"((a)[0]), "r"((a)[1]), "r"((a)[2]), "r"((a)[3]), "r"(b0_), "r"(b1_))

// ---- scratch (allocation-free: __device__ globals) ------------------------
__device__ float g_L[M_IND * M_IND];
__device__ float g_W[M_IND * M_IND];
__device__ float g_Zd[NB * BS * BS];
__device__ float g_tmp[512 * 512];
__device__ float g_xs[M_IND * D_DIM];
__device__ float g_nm[M_IND];
__device__ float g_a1[M_IND];
__device__ float g_a2[M_IND];
__device__ float g_q[8 * SW];
__device__ float g_mm[8 * SW];
__device__ float g_vv[8 * SW];
__device__ __nv_bfloat16 g_Whi[M_IND * M_IND];
__device__ __nv_bfloat16 g_Wlo[M_IND * M_IND];
__device__ __nv_bfloat16 g_Shi[(size_t)SW * M_IND];   // [n][k] layout
__device__ __nv_bfloat16 g_Slo[(size_t)SW * M_IND];
__device__ unsigned g_cnt = 0;
__device__ volatile unsigned g_epoch = 0;

// ---------------------------------------------------------------------------
// Software grid barrier (monotonic epoch: safe across graph replays)
// ---------------------------------------------------------------------------
__device__ __forceinline__ void gbar(unsigned& sense) {
    __syncthreads();
    if (threadIdx.x == 0) {
        unsigned target = sense + 1;
        __threadfence();
        unsigned old = atomicAdd(&g_cnt, 1u);
        if (old == NBLK - 1) {
            atomicExch(&g_cnt, 0u);
            __threadfence();
            g_epoch = target;
        } else {
            while (g_epoch < target) { __nanosleep(40); }
            __threadfence();
        }
    }
    __syncthreads();
    sense += 1;
}

// ---------------------------------------------------------------------------
// 64x64 Cholesky factor + triangular inverse, rank-8 panel version.
// Lb in: symmetric block (lower valid). Out: Lb = L (lower), Zb = L^{-1},
// g_Zd[kout] = Zb. 256 threads. Few __syncthreads.
// ---------------------------------------------------------------------------
#define TRI(r, c) ((r) * ((r) + 1) / 2 + (c))
__device__ __noinline__ void factor_inverse(float (&Lb)[BS][BS + 1],
                                            float (&Zb)[BS][BS + 1], int kout) {
    __shared__ float Mtmp[7 * 64];
    int tid = threadIdx.x;

    // zero Zb (upper parts must be 0 in output)
    for (int e = tid; e < BS * BS; e += 256)
        Zb[e / BS][e % BS] = 0.f;

    for (int j0 = 0; j0 < BS; j0 += 8) {
        // 1. redundant per-thread 8x8 factor + inverse (registers, no syncs)
        float a[36], z[36];
#pragma unroll
        for (int r = 0; r < 8; r++)
#pragma unroll
            for (int c = 0; c <= r; c++)
                a[TRI(r, c)] = Lb[j0 + r][j0 + c];
#pragma unroll
        for (int p = 0; p < 8; p++) {
            float d = sqrtf(a[TRI(p, p)]);
            a[TRI(p, p)] = d;
            float inv = 1.f / d;
#pragma unroll
            for (int r = p + 1; r < 8; r++) a[TRI(r, p)] *= inv;
#pragma unroll
            for (int r = p + 1; r < 8; r++)
#pragma unroll
                for (int c = p + 1; c <= r; c++)
                    a[TRI(r, c)] -= a[TRI(r, p)] * a[TRI(c, p)];
        }
#pragma unroll
        for (int c = 0; c < 8; c++) {
            z[TRI(c, c)] = 1.f / a[TRI(c, c)];
#pragma unroll
            for (int r = c + 1; r < 8; r++) {
                float s = 0.f;
#pragma unroll
                for (int k = c; k < r; k++) s += a[TRI(r, k)] * z[TRI(k, c)];
                z[TRI(r, c)] = -s / a[TRI(r, r)];
            }
        }
        __syncthreads();   // all threads done reading diag block

        // write factored diag into Lb, its inverse into Zb diag slot
        if (tid < 8) {
#pragma unroll
            for (int c = 0; c < 8; c++) {
                Lb[j0 + tid][j0 + c] = (c <= tid) ? a[TRI(tid, c)] : 0.f;
                Zb[j0 + tid][j0 + c] = (c <= tid) ? z[TRI(tid, c)] : 0.f;
            }
        }
        int R = BS - j0 - 8;
        // 2. panel solve: L21 = A21 * L11^{-T}; out[c] = sum_{t<=c} A[t]*z[c][t]
        if (tid < R) {
            int r = j0 + 8 + tid;
            float av[8];
#pragma unroll
            for (int t = 0; t < 8; t++) av[t] = Lb[r][j0 + t];
#pragma unroll
            for (int c = 0; c < 8; c++) {
                float s = 0.f;
#pragma unroll
                for (int t = 0; t <= c; t++) s += av[t] * z[TRI(c, t)];
                Lb[r][j0 + c] = s;
            }
        }
        __syncthreads();
        // 3. trailing rank-8 update (lower only)
        if (R > 0) {
            int tot = R * R;
            for (int e = tid; e < tot; e += 256) {
                int rr = e / R, cc = e % R;
                if (cc <= rr) {
                    int r = j0 + 8 + rr, c = j0 + 8 + cc;
                    float s = Lb[r][c];
#pragma unroll
                    for (int t = 0; t < 8; t++) s -= Lb[r][j0 + t] * Lb[c][j0 + t];
                    Lb[r][c] = s;
                }
            }
        }
        __syncthreads();
    }

    // blocked inversion: for bi>bj: Z_ij = -Z_ii * (sum_{k=bj..bi-1} L_ik Z_kj)
    for (int bi = 1; bi < 8; bi++) {
        int tot = bi * 64;
        for (int e = tid; e < tot; e += 256) {
            int bj = e >> 6, rc = e & 63, r = rc >> 3, c = rc & 7;
            float s = 0.f;
            for (int k = bj * 8; k < bi * 8; k++)
                s += Lb[bi * 8 + r][k] * Zb[k][bj * 8 + c];
            Mtmp[e] = s;
        }
        __syncthreads();
        for (int e = tid; e < tot; e += 256) {
            int bj = e >> 6, rc = e & 63, r = rc >> 3, c = rc & 7;
            float s = 0.f;
#pragma unroll
            for (int t = 0; t < 8; t++)
                s += Zb[bi * 8 + r][bi * 8 + t] * Mtmp[bj * 64 + t * 8 + c];
            Zb[bi * 8 + r][bj * 8 + c] = -s;
        }
        __syncthreads();
    }

    for (int e = tid; e < BS * BS; e += 256)
        g_Zd[kout * BS * BS + e] = Zb[e / BS][e % BS];
    __syncthreads();
}

// ---------------------------------------------------------------------------
// Persistent kernel: K_mm -> Cholesky(L, Zd) -> W = L^{-1} -> a1, a2
// ---------------------------------------------------------------------------
__global__ void __launch_bounds__(256) fact_kernel(const float* __restrict__ xm,
                                                   const float* __restrict__ qu,
                                                   const float* __restrict__ ch,
                                                   const float* __restrict__ ls,
                                                   const float* __restrict__ sv) {
    __shared__ float SA[BS][BS + 1];
    __shared__ float SB[BS][BS + 1];
    __shared__ unsigned s0;
    int tid = threadIdx.x, bid = blockIdx.x;
    if (tid == 0) s0 = g_epoch;
    __syncthreads();
    unsigned sense = s0;

    int gthread = bid * 256 + tid;
    int tx = tid % 16, ty = tid / 16;

    // phase: pre-scaled xm rows + norms
    for (int m = gthread; m < M_IND; m += NBLK * 256) {
        float nrm = 0.f;
#pragma unroll
        for (int d = 0; d < D_DIM; d++) {
            float il = 1.f / (fabsf(ls[d]) + EPSV);
            float v = xm[m * D_DIM + d] * il;
            g_xs[m * D_DIM + d] = v;
            nrm += v * v;
        }
        g_nm[m] = nrm;
    }
    gbar(sense);

    // phase: K_mm lower tiles, smem-tiled (coalesced)
    float svv = fabsf(sv[0]);
    for (int x = bid; x < NB * (NB + 1) / 2; x += NBLK) {
        int br = 0;
        while ((br + 1) * (br + 2) / 2 <= x) br++;
        int bc = x - br * (br + 1) / 2;
        for (int e = tid; e < 64 * D_DIM; e += 256) {
            int i = e >> 4, d = e & 15;
            SA[i][d] = g_xs[(br * 64 + i) * D_DIM + d];
            SB[i][d] = g_xs[(bc * 64 + i) * D_DIM + d];
        }
        if (tid < 64) {
            SA[tid][16] = g_nm[br * 64 + tid];
            SB[tid][16] = g_nm[bc * 64 + tid];
        }
        __syncthreads();
        float dot[4][4] = {};
#pragma unroll
        for (int d = 0; d < D_DIM; d++) {
            float av[4], bv[4];
#pragma unroll
            for (int ii = 0; ii < 4; ii++) av[ii] = SA[ty * 4 + ii][d];
#pragma unroll
            for (int jj = 0; jj < 4; jj++) bv[jj] = SB[tx * 4 + jj][d];
#pragma unroll
            for (int ii = 0; ii < 4; ii++)
#pragma unroll
                for (int jj = 0; jj < 4; jj++) dot[ii][jj] += av[ii] * bv[jj];
        }
#pragma unroll
        for (int ii = 0; ii < 4; ii++) {
            int gr = br * 64 + ty * 4 + ii;
            float nr = SA[ty * 4 + ii][16];
#pragma unroll
            for (int jj = 0; jj < 4; jj++) {
                int gc = bc * 64 + tx * 4 + jj;
                float d2 = fmaxf(nr + SB[tx * 4 + jj][16] - 2.f * dot[ii][jj], 0.f);
                float v = svv * __expf(-0.5f * d2);
                if (gr == gc) v += JITTER;
                g_L[(size_t)gr * M_IND + gc] = v;
            }
        }
        __syncthreads();
    }
    gbar(sense);

    if (bid == 0) {
        for (int e = tid; e < BS * BS; e += 256)
            SA[e / BS][e % BS] = g_L[(size_t)(e / BS) * M_IND + (e % BS)];
        __syncthreads();
        factor_inverse(SA, SB, 0);
    }
    gbar(sense);

    for (int k = 0; k < NB - 1; k++) {
        int o = k * BS, t = NB - 1 - k;

        // panel phase: P = A * Zd_k^T
        for (int pidx = bid; pidx < t; pidx += NBLK) {
            int r0 = o + BS + pidx * BS;
            for (int e = tid; e < BS * BS; e += 256) {
                int i = e / BS, j = e % BS;
                SA[i][j] = g_L[(size_t)(r0 + i) * M_IND + o + j];
                SB[i][j] = g_Zd[k * BS * BS + e];
            }
            __syncthreads();
            float acc[4][4] = {};
            for (int c = 0; c < BS; c++) {
                float a[4], b[4];
#pragma unroll
                for (int ii = 0; ii < 4; ii++) a[ii] = SA[ty * 4 + ii][c];
#pragma unroll
                for (int jj = 0; jj < 4; jj++) b[jj] = SB[tx * 4 + jj][c];
#pragma unroll
                for (int ii = 0; ii < 4; ii++)
#pragma unroll
                    for (int jj = 0; jj < 4; jj++) acc[ii][jj] += a[ii] * b[jj];
            }
#pragma unroll
            for (int ii = 0; ii < 4; ii++)
#pragma unroll
                for (int jj = 0; jj < 4; jj++)
                    g_L[(size_t)(r0 + ty * 4 + ii) * M_IND + o + tx * 4 + jj] = acc[ii][jj];
            __syncthreads();
        }
        gbar(sense);

        // syrk phase (+ fused diag factor for k+1 on CTA 0)
        if (bid == 0) {
            int bi = k + 1;
            for (int e = tid; e < BS * BS; e += 256) {
                int i = e / BS, j = e % BS;
                SB[i][j] = g_L[(size_t)(bi * BS + i) * M_IND + o + j];
            }
            __syncthreads();
            float acc[4][4];
#pragma unroll
            for (int ii = 0; ii < 4; ii++)
#pragma unroll
                for (int jj = 0; jj < 4; jj++)
                    acc[ii][jj] = g_L[(size_t)(bi * BS + ty * 4 + ii) * M_IND + bi * BS + tx * 4 + jj];
            for (int c = 0; c < BS; c++) {
                float a[4], b[4];
#pragma unroll
                for (int ii = 0; ii < 4; ii++) a[ii] = SB[ty * 4 + ii][c];
#pragma unroll
                for (int jj = 0; jj < 4; jj++) b[jj] = SB[tx * 4 + jj][c];
#pragma unroll
                for (int ii = 0; ii < 4; ii++)
#pragma unroll
                    for (int jj = 0; jj < 4; jj++) acc[ii][jj] -= a[ii] * b[jj];
            }
            __syncthreads();
#pragma unroll
            for (int ii = 0; ii < 4; ii++)
#pragma unroll
                for (int jj = 0; jj < 4; jj++)
                    SA[ty * 4 + ii][tx * 4 + jj] = acc[ii][jj];
            __syncthreads();
            factor_inverse(SA, SB, k + 1);
        } else {
            int ntile = t * (t + 1) / 2;
            for (int x = bid; x < ntile; x += NBLK - 1) {
                int r = 0;
                while ((r + 1) * (r + 2) / 2 <= x) r++;
                int c = x - r * (r + 1) / 2;
                int bi = k + 1 + r, bj = k + 1 + c;
                for (int e = tid; e < BS * BS; e += 256) {
                    int i = e / BS, j = e % BS;
                    SA[i][j] = g_L[(size_t)(bi * BS + i) * M_IND + o + j];
                    SB[i][j] = g_L[(size_t)(bj * BS + i) * M_IND + o + j];
                }
                __syncthreads();
                float acc[4][4];
#pragma unroll
                for (int ii = 0; ii < 4; ii++)
#pragma unroll
                    for (int jj = 0; jj < 4; jj++)
                        acc[ii][jj] = g_L[(size_t)(bi * BS + ty * 4 + ii) * M_IND + bj * BS + tx * 4 + jj];
                for (int cc = 0; cc < BS; cc++) {
                    float a[4], b[4];
#pragma unroll
                    for (int ii = 0; ii < 4; ii++) a[ii] = SA[ty * 4 + ii][cc];
#pragma unroll
                    for (int jj = 0; jj < 4; jj++) b[jj] = SB[tx * 4 + jj][cc];
#pragma unroll
                    for (int ii = 0; ii < 4; ii++)
#pragma unroll
                        for (int jj = 0; jj < 4; jj++) acc[ii][jj] -= a[ii] * b[jj];
                }
#pragma unroll
                for (int ii = 0; ii < 4; ii++)
#pragma unroll
                    for (int jj = 0; jj < 4; jj++)
                        g_L[(size_t)(bi * BS + ty * 4 + ii) * M_IND + bj * BS + tx * 4 + jj] = acc[ii][jj];
                __syncthreads();
            }
        }
        gbar(sense);
    }

    // winit: W = blockdiag(Zd)
    for (int idx = gthread; idx < M_IND * M_IND; idx += NBLK * 256) {
        int r = idx / M_IND, c = idx % M_IND;
        float v = 0.f;
        if (r / BS == c / BS)
            v = g_Zd[(r / BS) * BS * BS + (r % BS) * BS + (c % BS)];
        g_W[idx] = v;
    }
    gbar(sense);

    // recursive doubling: W21 = -W22 (L21 W11)
    for (int l = 0; l < 4; l++) {
        int s = 64 << l, tt = 1 << l, pairs = 8 >> l;
        int tiles = pairs * tt * tt;

        for (int x = bid; x < tiles; x += NBLK) {
            int p = x / (tt * tt), rem = x % (tt * tt), tr = rem / tt, tc = rem % tt;
            int base = p * 2 * s;
            float acc[4][4] = {};
            for (int k0 = tc * BS; k0 < s; k0 += BS) {
                for (int e = tid; e < BS * BS; e += 256) {
                    int i = e / BS, j = e % BS;
                    SA[i][j] = g_L[(size_t)(base + s + tr * BS + i) * M_IND + base + k0 + j];
                    SB[i][j] = g_W[(size_t)(base + k0 + i) * M_IND + base + tc * BS + j];
                }
                __syncthreads();
                for (int c = 0; c < BS; c++) {
                    float a[4], b[4];
#pragma unroll
                    for (int ii = 0; ii < 4; ii++) a[ii] = SA[ty * 4 + ii][c];
#pragma unroll
                    for (int jj = 0; jj < 4; jj++) b[jj] = SB[c][tx * 4 + jj];
#pragma unroll
                    for (int ii = 0; ii < 4; ii++)
#pragma unroll
                        for (int jj = 0; jj < 4; jj++) acc[ii][jj] += a[ii] * b[jj];
                }
                __syncthreads();
            }
#pragma unroll
            for (int ii = 0; ii < 4; ii++)
#pragma unroll
                for (int jj = 0; jj < 4; jj++)
                    g_tmp[(size_t)p * s * s + (tr * BS + ty * 4 + ii) * s + tc * BS + tx * 4 + jj]
                        = acc[ii][jj];
            __syncthreads();
        }
        gbar(sense);

        for (int x = bid; x < tiles; x += NBLK) {
            int p = x / (tt * tt), rem = x % (tt * tt), tr = rem / tt, tc = rem % tt;
            int base = p * 2 * s;
            float acc[4][4] = {};
            for (int k0 = 0; k0 <= tr * BS; k0 += BS) {
                for (int e = tid; e < BS * BS; e += 256) {
                    int i = e / BS, j = e % BS;
                    SA[i][j] = g_W[(size_t)(base + s + tr * BS + i) * M_IND + base + s + k0 + j];
                    SB[i][j] = g_tmp[(size_t)p * s * s + (k0 + i) * s + tc * BS + j];
                }
                __syncthreads();
                for (int c = 0; c < BS; c++) {
                    float a[4], b[4];
#pragma unroll
                    for (int ii = 0; ii < 4; ii++) a[ii] = SA[ty * 4 + ii][c];
#pragma unroll
                    for (int jj = 0; jj < 4; jj++) b[jj] = SB[c][tx * 4 + jj];
#pragma unroll
                    for (int ii = 0; ii < 4; ii++)
#pragma unroll
                        for (int jj = 0; jj < 4; jj++) acc[ii][jj] += a[ii] * b[jj];
                }
                __syncthreads();
            }
#pragma unroll
            for (int ii = 0; ii < 4; ii++)
#pragma unroll
                for (int jj = 0; jj < 4; jj++)
                    g_W[(size_t)(base + s + tr * BS + ty * 4 + ii) * M_IND + base + tc * BS + tx * 4 + jj]
                        = -acc[ii][jj];
            __syncthreads();
        }
        gbar(sense);
    }

    // a1 = W qu, a2 = W chole
    int wid = gthread / 32, lane = tid % 32;
    for (int r = wid; r < M_IND; r += NBLK * 8) {
        float s1 = 0.f, s2 = 0.f;
        for (int c = lane; c <= r; c += 32) {
            float w = g_W[(size_t)r * M_IND + c];
            s1 += w * qu[c];
            s2 += w * ch[c];
        }
#pragma unroll
        for (int off = 16; off; off >>= 1) {
            s1 += __shfl_down_sync(0xffffffff, s1, off);
            s2 += __shfl_down_sync(0xffffffff, s2, off);
        }
        if (lane == 0) { g_a1[r] = s1; g_a2[r] = s2; }
    }
}

// ---------------------------------------------------------------------------
// W -> bf16 hi/lo split
// ---------------------------------------------------------------------------
__global__ void wconv() {
    int idx = blockIdx.x * 256 + threadIdx.x;
    if (idx >= M_IND * M_IND) return;
    float w = g_W[idx];
    __nv_bfloat16 h = __float2bfloat16(w);
    g_Whi[idx] = h;
    g_Wlo[idx] = __float2bfloat16(w - __bfloat162float(h));
}

// ---------------------------------------------------------------------------
// init_S: Shi/Slo[n][k] = bf16 split of k(Xte_n, xm_k); padding rows = 0
// ---------------------------------------------------------------------------
__global__ void init_S(const float* __restrict__ Xte, const float* __restrict__ ls,
                       const float* __restrict__ sv) {
    __shared__ float Xs[64][D_DIM + 1];
    __shared__ float Ms[32][D_DIM + 1];
    int n0 = blockIdx.x * 64, m0 = blockIdx.y * 32;
    int tid = threadIdx.x;

    for (int e = tid; e < 64 * D_DIM; e += 256) {
        int i = e / D_DIM, d = e % D_DIM;
        int n = n0 + i;
        float il = 1.f / (fabsf(ls[d]) + EPSV);
        Xs[i][d] = (n < N_TE) ? Xte[n * D_DIM + d] * il : 0.f;
    }
    for (int e = tid; e < 32 * D_DIM; e += 256) {
        int i = e / D_DIM, d = e % D_DIM;
        Ms[i][d] = g_xs[(m0 + i) * D_DIM + d];
    }
    __syncthreads();

    float svv = fabsf(sv[0]);
    int tx = tid % 64, ty = tid / 64;
    int n = n0 + tx;
    __align__(16) __nv_bfloat16 h8[8];
    __align__(16) __nv_bfloat16 l8[8];
#pragma unroll
    for (int mi = 0; mi < 8; mi++) {
        int ml = ty * 8 + mi;
        float outv = 0.f;
        if (n < N_TE) {
            float d2 = 0.f;
#pragma unroll
            for (int d = 0; d < D_DIM; d++) {
                float diff = Xs[tx][d] - Ms[ml][d];
                d2 += diff * diff;
            }
            outv = svv * __expf(-0.5f * d2);
        }
        __nv_bfloat16 h = __float2bfloat16(outv);
        h8[mi] = h;
        l8[mi] = __float2bfloat16(outv - __bfloat162float(h));
    }
    size_t off = (size_t)n * M_IND + m0 + ty * 8;
    *(uint4*)&g_Shi[off] = *(uint4*)h8;
    *(uint4*)&g_Slo[off] = *(uint4*)l8;
}

// ---------------------------------------------------------------------------
// Warp-MMA bf16 GEMM + fused epilogue (unchanged from round 5 pass).
// ---------------------------------------------------------------------------
#define STG_BYTES 65536
__global__ void __launch_bounds__(256) gemm_tc() {
    extern __shared__ __align__(1024) char dsm[];
    __shared__ float Rq[8][32], Rm[8][32], Rv[8][32];
    __shared__ float a1s[128], a2s[128];

    const uint32_t sbase = smem_to_u32(dsm);
    int tid = threadIdx.x, wid = tid >> 5, lane = tid & 31;
    int n0 = blockIdx.x * 128;
    int mb = 7 - (int)blockIdx.y;
    int m0 = mb * 128;
    int nchunks = (m0 + 128) >> 6;

    if (tid < 128) { a1s[tid] = g_a1[m0 + tid]; a2s[tid] = g_a2[m0 + tid]; }

    int wm = (wid >> 2) * 64;
    int wn = (wid & 3) * 32;
    int lrow16 = lane & 15, lhalf = lane >> 4;

    float acc[4][4][4];
#pragma unroll
    for (int i = 0; i < 4; i++)
#pragma unroll
        for (int j = 0; j < 4; j++)
#pragma unroll
            for (int r = 0; r < 4; r++) acc[i][j][r] = 0.f;

    for (int c = 0; c < nchunks + 1; c++) {
        if (c < nchunks) {
            int k0 = c << 6;
            uint32_t buf = sbase + (uint32_t)(c & 1) * STG_BYTES;
#pragma unroll
            for (int it = 0; it < 4; it++) {
                int e = tid + it * 256;
                int row = e >> 3, ch = e & 7;
                uint32_t soff = (uint32_t)(row * 128 + ((ch ^ (row & 7)) << 4));
                size_t wsrc = (size_t)(m0 + row) * M_IND + k0 + ch * 8;
                size_t ssrc = (size_t)(n0 + row) * M_IND + k0 + ch * 8;
                CPA(buf + soff,         &g_Whi[wsrc]);
                CPA(buf + 16384 + soff, &g_Wlo[wsrc]);
                CPA(buf + 32768 + soff, &g_Shi[ssrc]);
                CPA(buf + 49152 + soff, &g_Slo[ssrc]);
            }
            CPC();
        }
        if (c == 0) continue;

        if (c < nchunks) { CPW1(); } else { CPW0(); }
        __syncthreads();

        int cc = c - 1;
        uint32_t buf = sbase + (uint32_t)(cc & 1) * STG_BYTES;
        uint32_t WHIa = buf, WLOa = buf + 16384, SHIa = buf + 32768, SLOa = buf + 49152;

#pragma unroll
        for (int kk = 0; kk < 4; kk++) {
            uint32_t A[4][4], Bf[2][4];
#pragma unroll
            for (int j2 = 0; j2 < 2; j2++) {
                int row = wn + j2 * 16 + lrow16;
                int ch = kk * 2 + lhalf;
                LDSM4(Bf[j2], SHIa + (uint32_t)(row * 128 + ((ch ^ (row & 7)) << 4)));
            }
#pragma unroll
            for (int i = 0; i < 4; i++) {
                int row = wm + i * 16 + lrow16;
                int ch = kk * 2 + lhalf;
                LDSM4(A[i], WHIa + (uint32_t)(row * 128 + ((ch ^ (row & 7)) << 4)));
            }
#pragma unroll
            for (int i = 0; i < 4; i++)
#pragma unroll
                for (int j = 0; j < 4; j++)
                    MMA16816(acc[i][j], A[i], Bf[j >> 1][j & 1], Bf[j >> 1][(j & 1) + 2]);
#pragma unroll
            for (int j2 = 0; j2 < 2; j2++) {
                int row = wn + j2 * 16 + lrow16;
                int ch = kk * 2 + lhalf;
                LDSM4(Bf[j2], SLOa + (uint32_t)(row * 128 + ((ch ^ (row & 7)) << 4)));
            }
#pragma unroll
            for (int i = 0; i < 4; i++)
#pragma unroll
                for (int j = 0; j < 4; j++)
                    MMA16816(acc[i][j], A[i], Bf[j >> 1][j & 1], Bf[j >> 1][(j & 1) + 2]);
#pragma unroll
            for (int i = 0; i < 4; i++) {
                int row = wm + i * 16 + lrow16;
                int ch = kk * 2 + lhalf;
                LDSM4(A[i], WLOa + (uint32_t)(row * 128 + ((ch ^ (row & 7)) << 4)));
            }
#pragma unroll
            for (int j2 = 0; j2 < 2; j2++) {
                int row = wn + j2 * 16 + lrow16;
                int ch = kk * 2 + lhalf;
                LDSM4(Bf[j2], SHIa + (uint32_t)(row * 128 + ((ch ^ (row & 7)) << 4)));
            }
#pragma unroll
            for (int i = 0; i < 4; i++)
#pragma unroll
                for (int j = 0; j < 4; j++)
                    MMA16816(acc[i][j], A[i], Bf[j >> 1][j & 1], Bf[j >> 1][(j & 1) + 2]);
        }
        __syncthreads();
    }

    // fused epilogue: q/mm/vv partials
    float a1r[8], a2r[8];
#pragma unroll
    for (int i = 0; i < 4; i++)
#pragma unroll
        for (int rh = 0; rh < 2; rh++) {
            int row = wm + i * 16 + (lane >> 2) + rh * 8;
            a1r[i * 2 + rh] = a1s[row];
            a2r[i * 2 + rh] = a2s[row];
        }

    float pq[8], pm[8], pv[8];
#pragma unroll
    for (int j = 0; j < 4; j++)
#pragma unroll
        for (int cbit = 0; cbit < 2; cbit++) {
            float q = 0.f, m = 0.f, v = 0.f;
#pragma unroll
            for (int i = 0; i < 4; i++)
#pragma unroll
                for (int rh = 0; rh < 2; rh++) {
                    float x = acc[i][j][rh * 2 + cbit];
                    q += x * x;
                    m += x * a1r[i * 2 + rh];
                    v += x * a2r[i * 2 + rh];
                }
            pq[j * 2 + cbit] = q; pm[j * 2 + cbit] = m; pv[j * 2 + cbit] = v;
        }
#pragma unroll
    for (int off = 4; off <= 16; off <<= 1)
#pragma unroll
        for (int s = 0; s < 8; s++) {
            pq[s] += __shfl_xor_sync(0xffffffff, pq[s], off);
            pm[s] += __shfl_xor_sync(0xffffffff, pm[s], off);
            pv[s] += __shfl_xor_sync(0xffffffff, pv[s], off);
        }
    if (lane < 4) {
#pragma unroll
        for (int j = 0; j < 4; j++)
#pragma unroll
            for (int cbit = 0; cbit < 2; cbit++) {
                int col = j * 8 + lane * 2 + cbit;
                Rq[wid][col] = pq[j * 2 + cbit];
                Rm[wid][col] = pm[j * 2 + cbit];
                Rv[wid][col] = pv[j * 2 + cbit];
            }
    }
    __syncthreads();
    if (tid < 128) {
        int n = tid;
        int w = n >> 5, cl = n & 31;
        g_q[mb * SW + n0 + n]  = Rq[w][cl] + Rq[w + 4][cl];
        g_mm[mb * SW + n0 + n] = Rm[w][cl] + Rm[w + 4][cl];
        g_vv[mb * SW + n0 + n] = Rv[w][cl] + Rv[w + 4][cl];
    }
}

// ---------------------------------------------------------------------------
// Final reduce over the 8 mb partials
// ---------------------------------------------------------------------------
__global__ void reduce_out(float* __restrict__ out, const float* __restrict__ sv) {
    int n = blockIdx.x * 256 + threadIdx.x;
    if (n >= N_TE) return;
    float q = 0.f, mm = 0.f, vv = 0.f;
#pragma unroll
    for (int mb = 0; mb < 8; mb++) {
        q  += g_q[mb * SW + n];
        mm += g_mm[mb * SW + n];
        vv += g_vv[mb * SW + n];
    }
    float svv = fabsf(sv[0]);
    out[n] = mm;
    out[N_TE + n] = svv - q + vv * vv;
}

// ---------------------------------------------------------------------------
extern "C" void kernel_launch(void* const* d_in, const int* in_sizes, int n_in,
                              void* d_out, int out_size) {
    const float* Xte = (const float*)d_in[0];
    const float* xm  = (const float*)d_in[1];
    const float* qu  = (const float*)d_in[2];
    const float* ch  = (const float*)d_in[3];
    const float* ls  = (const float*)d_in[4];
    const float* sv  = (const float*)d_in[5];
    float* out = (float*)d_out;

    static bool attr_done = false;
    if (!attr_done) {
        cudaFuncSetAttribute(gemm_tc, cudaFuncAttributeMaxDynamicSharedMemorySize,
                             2 * STG_BYTES);
        attr_done = true;
    }

    fact_kernel<<<NBLK, 256>>>(xm, qu, ch, ls, sv);
    wconv<<<(M_IND * M_IND + 255) / 256, 256>>>();
    init_S<<<dim3(SW / 64, M_IND / 32), 256>>>(Xte, ls, sv);
    gemm_tc<<<dim3(SW / 128, 8), 256, 2 * STG_BYTES>>>();
    reduce_out<<<(N_TE + 255) / 256, 256>>>(out, sv);
}